// round 4
// baseline (speedup 1.0000x reference)
#include <cuda_runtime.h>

// ---------------- problem constants ----------------
#define N_A   30000
#define N_B   30000
#define VV    2
#define DD    128
#define EE    480000
#define PP    2

#define ROWS_H 60000    // N_A*V   (also N_B*V)
#define ROWS_X 120000   // N_A*V*P

#define WT_LD 132       // padded smem row for W^T (floats)
// dynamic smem: W^T (128x132 f32) + per-warp x staging (8 warps * 4 rows * 128 ull)
#define SMEM_BYTES (DD*WT_LD*4 + 8*4*DD*8)   // 67584 + 32768 = 100352

// ---------------- scratch (device globals; no allocation allowed) ----------------
__device__ int g_cnt_ab[N_B];
__device__ int g_cnt_ba[N_A];
__device__ int g_ptr_ab[N_B + 1];
__device__ int g_ptr_ba[N_A + 1];
__device__ int g_eid_ab[EE];
__device__ int g_eid_ba[EE];

__device__ float g_hB  [(size_t)N_B * VV * DD];   // l2norm(spmm(feat_A)) at B
__device__ float g_hABA[(size_t)N_A * VV * DD];   // l2norm(spmm(g_hB)) at A
__device__ float g_hBA [(size_t)N_A * VV * DD];   // l2norm(spmm(feat_B)) at A
__device__ float g_x[(size_t)ROWS_X * DD];        // stacked [n][v][p][d]
__device__ float g_q[(size_t)ROWS_X * DD];
__device__ float g_k[(size_t)ROWS_X * DD];
__device__ float g_v[(size_t)ROWS_X * DD];
__device__ float g_o[(size_t)ROWS_X * DD];

// ---------------- helpers ----------------
static __device__ __forceinline__ float warp_sum(float v) {
#pragma unroll
    for (int o = 16; o > 0; o >>= 1) v += __shfl_xor_sync(0xffffffffu, v, o);
    return v;
}

// packed f32x2 FMA (B300: FFMA2, 2x scalar FFMA throughput)
static __device__ __forceinline__ unsigned long long pk2(float x) {
    unsigned long long r;
    asm("mov.b64 %0, {%1, %1};" : "=l"(r) : "f"(x));
    return r;
}
static __device__ __forceinline__ void ffma2(unsigned long long& d,
                                             unsigned long long a,
                                             unsigned long long b) {
    asm("fma.rn.f32x2 %0, %1, %2, %0;" : "+l"(d) : "l"(a), "l"(b));
}
static __device__ __forceinline__ float2 upk2(unsigned long long a) {
    float2 f;
    asm("mov.b64 {%0, %1}, %2;" : "=f"(f.x), "=f"(f.y) : "l"(a));
    return f;
}

static __device__ __forceinline__ void stage_Wt(const float* __restrict__ W, float* sWt) {
    // sWt[k][j] = W[j][k], padded row WT_LD
    for (int idx = threadIdx.x; idx < DD * DD; idx += blockDim.x) {
        int j = idx >> 7, k = idx & 127;
        sWt[k * WT_LD + j] = W[idx];
    }
}

// ---------------- CSR build ----------------
__global__ void k_zero_cnt() {
    int i = blockIdx.x * blockDim.x + threadIdx.x;
    if (i < N_B) g_cnt_ab[i] = 0;
    if (i < N_A) g_cnt_ba[i] = 0;
}

__global__ void k_hist(const int* __restrict__ dst_ab, const int* __restrict__ dst_ba) {
    int e = blockIdx.x * blockDim.x + threadIdx.x;
    if (e < EE) {
        atomicAdd(&g_cnt_ab[dst_ab[e]], 1);
        atomicAdd(&g_cnt_ba[dst_ba[e]], 1);
    }
}

__global__ void k_scan() {
    __shared__ int ssum[1024];
    const int n = N_A;  // both 30000
    int* cnt = (blockIdx.x == 0) ? g_cnt_ab : g_cnt_ba;
    int* ptr = (blockIdx.x == 0) ? g_ptr_ab : g_ptr_ba;
    int t = threadIdx.x;
    const int chunk = (n + 1023) / 1024;
    int b0 = t * chunk;
    int b1 = min(b0 + chunk, n);
    int s = 0;
    for (int i = b0; i < b1; i++) s += cnt[i];
    ssum[t] = s;
    __syncthreads();
#pragma unroll
    for (int off = 1; off < 1024; off <<= 1) {
        int v = (t >= off) ? ssum[t - off] : 0;
        __syncthreads();
        ssum[t] += v;
        __syncthreads();
    }
    int run = (t == 0) ? 0 : ssum[t - 1];
    for (int i = b0; i < b1; i++) { ptr[i] = run; run += cnt[i]; }
    if (t == 1023) ptr[n] = ssum[1023];
}

__global__ void k_scatter(const int* __restrict__ dst_ab, const int* __restrict__ dst_ba) {
    int e = blockIdx.x * blockDim.x + threadIdx.x;
    if (e < EE) {
        int d = dst_ab[e];
        int p = g_ptr_ab[d] + atomicAdd(&g_cnt_ab[d], 1);
        g_eid_ab[p] = e;
        d = dst_ba[e];
        p = g_ptr_ba[d] + atomicAdd(&g_cnt_ba[d], 1);
        g_eid_ba[p] = e;
    }
}

// ---------------- spmm + fused l2norm ----------------
// warp per (node_B, v): h_B = l2norm( sum_e feat_A[src]*val )
__global__ void k_spmm_ab(const float* __restrict__ feat_A,
                          const int* __restrict__ src_ab,
                          const float* __restrict__ val_ab) {
    int w = (blockIdx.x * blockDim.x + threadIdx.x) >> 5;
    int lane = threadIdx.x & 31;
    if (w >= N_B * VV) return;
    int n = w >> 1, v = w & 1;
    int beg = g_ptr_ab[n], end = g_ptr_ab[n + 1];
    float4 acc = make_float4(0.f, 0.f, 0.f, 0.f);
    for (int c = beg; c < end; c += 32) {
        int m = min(32, end - c);
        int s = 0; float vv = 0.f;
        if (lane < m) { int e = g_eid_ab[c + lane]; s = src_ab[e]; vv = val_ab[e]; }
        for (int j = 0; j < m; j++) {
            int sj = __shfl_sync(0xffffffffu, s, j);
            float vj = __shfl_sync(0xffffffffu, vv, j);
            const float4 f = *reinterpret_cast<const float4*>(
                feat_A + (((size_t)sj * VV + v) << 7) + (lane << 2));
            acc.x = fmaf(f.x, vj, acc.x);
            acc.y = fmaf(f.y, vj, acc.y);
            acc.z = fmaf(f.z, vj, acc.z);
            acc.w = fmaf(f.w, vj, acc.w);
        }
    }
    float sq = warp_sum(acc.x * acc.x + acc.y * acc.y + acc.z * acc.z + acc.w * acc.w);
    float inv = 1.f / fmaxf(sqrtf(sq), 1e-12f);
    *reinterpret_cast<float4*>(g_hB + (((size_t)n * VV + v) << 7) + (lane << 2)) =
        make_float4(acc.x * inv, acc.y * inv, acc.z * inv, acc.w * inv);
}

// warp per (node_A, v): h_ABA from g_hB, h_BA from feat_B — same edges, fused
__global__ void k_spmm_ba(const float* __restrict__ feat_B,
                          const int* __restrict__ src_ba,
                          const float* __restrict__ val_ba) {
    int w = (blockIdx.x * blockDim.x + threadIdx.x) >> 5;
    int lane = threadIdx.x & 31;
    if (w >= N_A * VV) return;
    int n = w >> 1, v = w & 1;
    int beg = g_ptr_ba[n], end = g_ptr_ba[n + 1];
    float4 a1 = make_float4(0.f, 0.f, 0.f, 0.f);
    float4 a2 = make_float4(0.f, 0.f, 0.f, 0.f);
    for (int c = beg; c < end; c += 32) {
        int m = min(32, end - c);
        int s = 0; float vv = 0.f;
        if (lane < m) { int e = g_eid_ba[c + lane]; s = src_ba[e]; vv = val_ba[e]; }
        for (int j = 0; j < m; j++) {
            int sj = __shfl_sync(0xffffffffu, s, j);
            float vj = __shfl_sync(0xffffffffu, vv, j);
            size_t off = (((size_t)sj * VV + v) << 7) + (lane << 2);
            const float4 f1 = *reinterpret_cast<const float4*>(g_hB + off);
            const float4 f2 = *reinterpret_cast<const float4*>(feat_B + off);
            a1.x = fmaf(f1.x, vj, a1.x); a1.y = fmaf(f1.y, vj, a1.y);
            a1.z = fmaf(f1.z, vj, a1.z); a1.w = fmaf(f1.w, vj, a1.w);
            a2.x = fmaf(f2.x, vj, a2.x); a2.y = fmaf(f2.y, vj, a2.y);
            a2.z = fmaf(f2.z, vj, a2.z); a2.w = fmaf(f2.w, vj, a2.w);
        }
    }
    size_t outoff = (((size_t)n * VV + v) << 7) + (lane << 2);
    float sq1 = warp_sum(a1.x * a1.x + a1.y * a1.y + a1.z * a1.z + a1.w * a1.w);
    float i1 = 1.f / fmaxf(sqrtf(sq1), 1e-12f);
    *reinterpret_cast<float4*>(g_hABA + outoff) =
        make_float4(a1.x * i1, a1.y * i1, a1.z * i1, a1.w * i1);
    float sq2 = warp_sum(a2.x * a2.x + a2.y * a2.y + a2.z * a2.z + a2.w * a2.w);
    float i2 = 1.f / fmaxf(sqrtf(sq2), 1e-12f);
    *reinterpret_cast<float4*>(g_hBA + outoff) =
        make_float4(a2.x * i2, a2.y * i2, a2.z * i2, a2.w * i2);
}

// ---------------- GEMM cores (W^T in smem, 4 rows/warp, f32x2 FMA) ----------------

// proj: relu(LN(in @ W^T + b)) -> g_x[.., which, :]   (in = g_hABA or g_hBA)
__global__ void k_proj(const float* __restrict__ Wm, const float* __restrict__ bm,
                       const float* __restrict__ gm, const float* __restrict__ bem,
                       int which) {
    extern __shared__ float sm[];
    float* sWt = sm;
    unsigned long long* sX = reinterpret_cast<unsigned long long*>(sm + DD * WT_LD);
    stage_Wt(Wm, sWt);
    int lane = threadIdx.x & 31, w = threadIdx.x >> 5;
    const float* in = which ? g_hBA : g_hABA;
    float4 b4  = *reinterpret_cast<const float4*>(bm  + (lane << 2));
    float4 g4  = *reinterpret_cast<const float4*>(gm  + (lane << 2));
    float4 be4 = *reinterpret_cast<const float4*>(bem + (lane << 2));
    __syncthreads();
    unsigned long long* xr = sX + (size_t)w * 4 * DD;
    int base = (blockIdx.x * (blockDim.x >> 5) + w) * 4;
    if (base >= ROWS_H) return;
#pragma unroll
    for (int r = 0; r < 4; r++) {
        const float* row = in + (size_t)(base + r) * DD;
#pragma unroll
        for (int c = 0; c < 4; c++)
            xr[r * DD + lane + 32 * c] = pk2(row[lane + 32 * c]);
    }
    __syncwarp();
    unsigned long long acc[4][2];
#pragma unroll
    for (int r = 0; r < 4; r++) { acc[r][0] = 0ull; acc[r][1] = 0ull; }
    const float* wp = sWt + (lane << 2);
#pragma unroll 4
    for (int k = 0; k < DD; k++) {
        ulonglong2 wv = *reinterpret_cast<const ulonglong2*>(wp + k * WT_LD);
#pragma unroll
        for (int r = 0; r < 4; r++) {
            unsigned long long xx = xr[r * DD + k];
            ffma2(acc[r][0], wv.x, xx);
            ffma2(acc[r][1], wv.y, xx);
        }
    }
#pragma unroll
    for (int r = 0; r < 4; r++) {
        float2 p0 = upk2(acc[r][0]), p1 = upk2(acc[r][1]);
        float4 t = make_float4(p0.x + b4.x, p0.y + b4.y, p1.x + b4.z, p1.y + b4.w);
        float mu = warp_sum(t.x + t.y + t.z + t.w) * (1.f / DD);
        float4 d = make_float4(t.x - mu, t.y - mu, t.z - mu, t.w - mu);
        float var = warp_sum(d.x * d.x + d.y * d.y + d.z * d.z + d.w * d.w) * (1.f / DD);
        float rs = rsqrtf(var + 1e-5f);
        float4 o = make_float4(fmaxf(d.x * rs * g4.x + be4.x, 0.f),
                               fmaxf(d.y * rs * g4.y + be4.y, 0.f),
                               fmaxf(d.z * rs * g4.z + be4.z, 0.f),
                               fmaxf(d.w * rs * g4.w + be4.w, 0.f));
        *reinterpret_cast<float4*>(
            g_x + ((size_t)(base + r) * PP + which) * DD + (lane << 2)) = o;
    }
}

// qkv: out = (g_x @ W^T + b) * scale, which: 0->q, 1->k, 2->v
__global__ void k_linear_qkv(const float* __restrict__ Wm, const float* __restrict__ bm,
                             int which, float scale) {
    extern __shared__ float sm[];
    float* sWt = sm;
    unsigned long long* sX = reinterpret_cast<unsigned long long*>(sm + DD * WT_LD);
    stage_Wt(Wm, sWt);
    int lane = threadIdx.x & 31, w = threadIdx.x >> 5;
    float* out = (which == 0) ? g_q : ((which == 1) ? g_k : g_v);
    float4 b4 = *reinterpret_cast<const float4*>(bm + (lane << 2));
    __syncthreads();
    unsigned long long* xr = sX + (size_t)w * 4 * DD;
    int base = (blockIdx.x * (blockDim.x >> 5) + w) * 4;
    if (base >= ROWS_X) return;
#pragma unroll
    for (int r = 0; r < 4; r++) {
        const float* row = g_x + (size_t)(base + r) * DD;
#pragma unroll
        for (int c = 0; c < 4; c++)
            xr[r * DD + lane + 32 * c] = pk2(row[lane + 32 * c]);
    }
    __syncwarp();
    unsigned long long acc[4][2];
#pragma unroll
    for (int r = 0; r < 4; r++) { acc[r][0] = 0ull; acc[r][1] = 0ull; }
    const float* wp = sWt + (lane << 2);
#pragma unroll 4
    for (int k = 0; k < DD; k++) {
        ulonglong2 wv = *reinterpret_cast<const ulonglong2*>(wp + k * WT_LD);
#pragma unroll
        for (int r = 0; r < 4; r++) {
            unsigned long long xx = xr[r * DD + k];
            ffma2(acc[r][0], wv.x, xx);
            ffma2(acc[r][1], wv.y, xx);
        }
    }
#pragma unroll
    for (int r = 0; r < 4; r++) {
        float2 p0 = upk2(acc[r][0]), p1 = upk2(acc[r][1]);
        float4 o = make_float4((p0.x + b4.x) * scale, (p0.y + b4.y) * scale,
                               (p1.x + b4.z) * scale, (p1.y + b4.w) * scale);
        *reinterpret_cast<float4*>(out + (size_t)(base + r) * DD + (lane << 2)) = o;
    }
}

// attention over P=2, H=4 heads of dh=32: warp per (n,v)
__global__ void k_attn() {
    int w = (blockIdx.x * blockDim.x + threadIdx.x) >> 5;
    int lane = threadIdx.x & 31;
    if (w >= ROWS_H) return;
    size_t r0 = (size_t)w * 2 * DD;
    size_t r1 = r0 + DD;
#pragma unroll
    for (int h = 0; h < 4; h++) {
        int off = h * 32 + lane;
        float q0 = g_q[r0 + off], q1 = g_q[r1 + off];
        float k0 = g_k[r0 + off], k1 = g_k[r1 + off];
        float v0 = g_v[r0 + off], v1 = g_v[r1 + off];
        float s00 = warp_sum(q0 * k0);
        float s01 = warp_sum(q0 * k1);
        float s10 = warp_sum(q1 * k0);
        float s11 = warp_sum(q1 * k1);
        float m0 = fmaxf(s00, s01), m1 = fmaxf(s10, s11);
        float e00 = expf(s00 - m0), e01 = expf(s01 - m0);
        float e10 = expf(s10 - m1), e11 = expf(s11 - m1);
        float i0 = 1.f / (e00 + e01), i1 = 1.f / (e10 + e11);
        g_o[r0 + off] = (e00 * i0) * v0 + (e01 * i0) * v1;
        g_o[r1 + off] = (e10 * i1) * v0 + (e11 * i1) * v1;
    }
}

// final: attn = g_o @ Wout^T + bout; t = LN(attn + g_x); y = mean over P -> d_out
__global__ void k_out(const float* __restrict__ Wm, const float* __restrict__ bm,
                      const float* __restrict__ gm, const float* __restrict__ bem,
                      float* __restrict__ outp) {
    extern __shared__ float sm[];
    float* sWt = sm;
    unsigned long long* sX = reinterpret_cast<unsigned long long*>(sm + DD * WT_LD);
    stage_Wt(Wm, sWt);
    int lane = threadIdx.x & 31, w = threadIdx.x >> 5;
    float4 b4  = *reinterpret_cast<const float4*>(bm  + (lane << 2));
    float4 g4  = *reinterpret_cast<const float4*>(gm  + (lane << 2));
    float4 be4 = *reinterpret_cast<const float4*>(bem + (lane << 2));
    __syncthreads();
    unsigned long long* xr = sX + (size_t)w * 4 * DD;
    int base = (blockIdx.x * (blockDim.x >> 5) + w) * 4;  // 4 rows = 2 (n,v) units
    if (base >= ROWS_X) return;
#pragma unroll
    for (int r = 0; r < 4; r++) {
        const float* row = g_o + (size_t)(base + r) * DD;
#pragma unroll
        for (int c = 0; c < 4; c++)
            xr[r * DD + lane + 32 * c] = pk2(row[lane + 32 * c]);
    }
    __syncwarp();
    unsigned long long acc[4][2];
#pragma unroll
    for (int r = 0; r < 4; r++) { acc[r][0] = 0ull; acc[r][1] = 0ull; }
    const float* wp = sWt + (lane << 2);
#pragma unroll 4
    for (int k = 0; k < DD; k++) {
        ulonglong2 wv = *reinterpret_cast<const ulonglong2*>(wp + k * WT_LD);
#pragma unroll
        for (int r = 0; r < 4; r++) {
            unsigned long long xx = xr[r * DD + k];
            ffma2(acc[r][0], wv.x, xx);
            ffma2(acc[r][1], wv.y, xx);
        }
    }
    float4 ys0 = make_float4(0.f, 0.f, 0.f, 0.f);
    float4 ys1 = make_float4(0.f, 0.f, 0.f, 0.f);
#pragma unroll
    for (int r = 0; r < 4; r++) {
        float2 p0 = upk2(acc[r][0]), p1 = upk2(acc[r][1]);
        float4 x4 = *reinterpret_cast<const float4*>(
            g_x + (size_t)(base + r) * DD + (lane << 2));
        float4 t = make_float4(p0.x + b4.x + x4.x, p0.y + b4.y + x4.y,
                               p1.x + b4.z + x4.z, p1.y + b4.w + x4.w);
        float mu = warp_sum(t.x + t.y + t.z + t.w) * (1.f / DD);
        float4 d = make_float4(t.x - mu, t.y - mu, t.z - mu, t.w - mu);
        float var = warp_sum(d.x * d.x + d.y * d.y + d.z * d.z + d.w * d.w) * (1.f / DD);
        float rs = rsqrtf(var + 1e-5f);
        float4 tn = make_float4(d.x * rs * g4.x + be4.x, d.y * rs * g4.y + be4.y,
                                d.z * rs * g4.z + be4.z, d.w * rs * g4.w + be4.w);
        if (r < 2) {
            ys0.x += tn.x; ys0.y += tn.y; ys0.z += tn.z; ys0.w += tn.w;
        } else {
            ys1.x += tn.x; ys1.y += tn.y; ys1.z += tn.z; ys1.w += tn.w;
        }
    }
    int u0 = base >> 1;
    *reinterpret_cast<float4*>(outp + (size_t)u0 * DD + (lane << 2)) =
        make_float4(ys0.x * 0.5f, ys0.y * 0.5f, ys0.z * 0.5f, ys0.w * 0.5f);
    *reinterpret_cast<float4*>(outp + (size_t)(u0 + 1) * DD + (lane << 2)) =
        make_float4(ys1.x * 0.5f, ys1.y * 0.5f, ys1.z * 0.5f, ys1.w * 0.5f);
}

// ---------------- launch ----------------
extern "C" void kernel_launch(void* const* d_in, const int* in_sizes, int n_in,
                              void* d_out, int out_size) {
    (void)in_sizes; (void)n_in; (void)out_size;
    const float* feat_A = (const float*)d_in[0];
    const float* feat_B = (const float*)d_in[1];
    const int*   src_ab = (const int*)d_in[2];
    const int*   dst_ab = (const int*)d_in[3];
    const float* val_ab = (const float*)d_in[4];
    const int*   src_ba = (const int*)d_in[5];
    const int*   dst_ba = (const int*)d_in[6];
    const float* val_ba = (const float*)d_in[7];
    const float* W1  = (const float*)d_in[8];
    const float* b1  = (const float*)d_in[9];
    const float* g1  = (const float*)d_in[10];
    const float* be1 = (const float*)d_in[11];
    const float* W2  = (const float*)d_in[12];
    const float* b2  = (const float*)d_in[13];
    const float* g2  = (const float*)d_in[14];
    const float* be2 = (const float*)d_in[15];
    const float* Win  = (const float*)d_in[16];
    const float* bin_ = (const float*)d_in[17];
    const float* Wout = (const float*)d_in[18];
    const float* bout = (const float*)d_in[19];
    const float* lng  = (const float*)d_in[20];
    const float* lnb  = (const float*)d_in[21];
    float* outp = (float*)d_out;

    cudaFuncSetAttribute(k_proj,       cudaFuncAttributeMaxDynamicSharedMemorySize, SMEM_BYTES);
    cudaFuncSetAttribute(k_linear_qkv, cudaFuncAttributeMaxDynamicSharedMemorySize, SMEM_BYTES);
    cudaFuncSetAttribute(k_out,        cudaFuncAttributeMaxDynamicSharedMemorySize, SMEM_BYTES);

    // CSR build (dst-grouped) for both edge sets
    k_zero_cnt<<<118, 256>>>();
    k_hist<<<1875, 256>>>(dst_ab, dst_ba);
    k_scan<<<2, 1024>>>();
    k_zero_cnt<<<118, 256>>>();
    k_scatter<<<1875, 256>>>(dst_ab, dst_ba);

    // spmm + fused l2norm
    k_spmm_ab<<<7500, 256>>>(feat_A, src_ab, val_ab);
    k_spmm_ba<<<7500, 256>>>(feat_B, src_ba, val_ba);

    // proj -> x (stacked)
    k_proj<<<1875, 256, SMEM_BYTES>>>(W1, b1, g1, be1, 0);
    k_proj<<<1875, 256, SMEM_BYTES>>>(W2, b2, g2, be2, 1);

    // qkv (q scaled by dh^-0.5 = 32^-0.5)
    const float qscale = 0.17677669529663687f;
    k_linear_qkv<<<3750, 256, SMEM_BYTES>>>(Win,             bin_,       0, qscale);
    k_linear_qkv<<<3750, 256, SMEM_BYTES>>>(Win + 128 * 128, bin_ + 128, 1, 1.0f);
    k_linear_qkv<<<3750, 256, SMEM_BYTES>>>(Win + 256 * 128, bin_ + 256, 2, 1.0f);

    // attention over P=2
    k_attn<<<7500, 256>>>();

    // Wout + residual + LN + mean over P
    k_out<<<3750, 256, SMEM_BYTES>>>(Wout, bout, lng, lnb, outp);
}

// round 5
// speedup vs baseline: 1.2582x; 1.2582x over previous
#include <cuda_runtime.h>

// ---------------- problem constants ----------------
#define N_A   30000
#define N_B   30000
#define VV    2
#define DD    128
#define EE    480000
#define PP    2

#define ROWS_H 60000    // N_A*V   (also N_B*V)
#define ROWS_X 120000   // N_A*V*P

// smem: proj/out kernels: W^T (128*128 f32 = 64KB) + x stage (8 warps*4 rows*128 ull = 32KB)
#define SMEM_PROJ (DD*DD*4 + 8*4*DD*8)           // 98304
// qkv kernel: 3x W^T (192KB) + x stage (32KB)
#define SMEM_QKV  (3*DD*DD*4 + 8*4*DD*8)         // 229376  (<= 232448 max)

// ---------------- scratch (device globals; no allocation allowed) ----------------
__device__ int g_cnt_ab[N_B];
__device__ int g_cnt_ba[N_A];
__device__ int g_ptr_ab[N_B + 1];
__device__ int g_ptr_ba[N_A + 1];
__device__ int   g_srcs_ab[EE];   // CSR-sorted src
__device__ float g_vals_ab[EE];   // CSR-sorted val
__device__ int   g_srcs_ba[EE];
__device__ float g_vals_ba[EE];

__device__ float g_hB  [(size_t)N_B * VV * DD];   // l2norm(spmm(feat_A)) at B
__device__ float g_hABA[(size_t)N_A * VV * DD];   // l2norm(spmm(g_hB)) at A
__device__ float g_hBA [(size_t)N_A * VV * DD];   // l2norm(spmm(feat_B)) at A
__device__ float g_x[(size_t)ROWS_X * DD];        // stacked [n][v][p][d]
__device__ float g_o[(size_t)ROWS_X * DD];        // attention output

// ---------------- helpers ----------------
static __device__ __forceinline__ float warp_sum(float v) {
#pragma unroll
    for (int o = 16; o > 0; o >>= 1) v += __shfl_xor_sync(0xffffffffu, v, o);
    return v;
}
static __device__ __forceinline__ float sum8(float v) {
    v += __shfl_xor_sync(0xffffffffu, v, 1);
    v += __shfl_xor_sync(0xffffffffu, v, 2);
    v += __shfl_xor_sync(0xffffffffu, v, 4);
    return v;
}

// packed f32x2 FMA (B300 FFMA2 path: 2x scalar FFMA throughput)
static __device__ __forceinline__ unsigned long long pk2(float x) {
    unsigned long long r;
    asm("mov.b64 %0, {%1, %1};" : "=l"(r) : "f"(x));
    return r;
}
static __device__ __forceinline__ void ffma2(unsigned long long& d,
                                             unsigned long long a,
                                             unsigned long long b) {
    asm("fma.rn.f32x2 %0, %1, %2, %0;" : "+l"(d) : "l"(a), "l"(b));
}
static __device__ __forceinline__ float2 upk2(unsigned long long a) {
    float2 f;
    asm("mov.b64 {%0, %1}, %2;" : "=f"(f.x), "=f"(f.y) : "l"(a));
    return f;
}
static __device__ __forceinline__ float4 acc2f4(const unsigned long long* a) {
    float2 p0 = upk2(a[0]), p1 = upk2(a[1]);
    return make_float4(p0.x, p0.y, p1.x, p1.y);
}

// ---------------- CSR build ----------------
__global__ void k_zero_cnt() {
    int i = blockIdx.x * blockDim.x + threadIdx.x;
    if (i < N_B) g_cnt_ab[i] = 0;
    if (i < N_A) g_cnt_ba[i] = 0;
}

__global__ void k_hist(const int* __restrict__ dst_ab, const int* __restrict__ dst_ba) {
    int e = blockIdx.x * blockDim.x + threadIdx.x;
    if (e < EE) {
        atomicAdd(&g_cnt_ab[dst_ab[e]], 1);
        atomicAdd(&g_cnt_ba[dst_ba[e]], 1);
    }
}

__global__ void k_scan() {
    __shared__ int ssum[1024];
    const int n = N_A;  // both 30000
    int* cnt = (blockIdx.x == 0) ? g_cnt_ab : g_cnt_ba;
    int* ptr = (blockIdx.x == 0) ? g_ptr_ab : g_ptr_ba;
    int t = threadIdx.x;
    const int chunk = (n + 1023) / 1024;
    int b0 = t * chunk;
    int b1 = min(b0 + chunk, n);
    int s = 0;
    for (int i = b0; i < b1; i++) s += cnt[i];
    ssum[t] = s;
    __syncthreads();
#pragma unroll
    for (int off = 1; off < 1024; off <<= 1) {
        int v = (t >= off) ? ssum[t - off] : 0;
        __syncthreads();
        ssum[t] += v;
        __syncthreads();
    }
    int run = (t == 0) ? 0 : ssum[t - 1];
    for (int i = b0; i < b1; i++) { ptr[i] = run; run += cnt[i]; }
    if (t == 1023) ptr[n] = ssum[1023];
}

__global__ void k_scatter(const int* __restrict__ dst_ab, const int* __restrict__ src_ab,
                          const float* __restrict__ val_ab,
                          const int* __restrict__ dst_ba, const int* __restrict__ src_ba,
                          const float* __restrict__ val_ba) {
    int e = blockIdx.x * blockDim.x + threadIdx.x;
    if (e < EE) {
        int d = dst_ab[e];
        int p = g_ptr_ab[d] + atomicAdd(&g_cnt_ab[d], 1);
        g_srcs_ab[p] = src_ab[e];
        g_vals_ab[p] = val_ab[e];
        d = dst_ba[e];
        p = g_ptr_ba[d] + atomicAdd(&g_cnt_ba[d], 1);
        g_srcs_ba[p] = src_ba[e];
        g_vals_ba[p] = val_ba[e];
    }
}

// ---------------- spmm + fused l2norm ----------------
// warp per (node_B, v): h_B = l2norm( sum_e feat_A[src]*val )
__global__ void k_spmm_ab(const float* __restrict__ feat_A) {
    int w = (blockIdx.x * blockDim.x + threadIdx.x) >> 5;
    int lane = threadIdx.x & 31;
    if (w >= N_B * VV) return;
    int n = w >> 1, v = w & 1;
    int beg = g_ptr_ab[n], end = g_ptr_ab[n + 1];
    float4 acc = make_float4(0.f, 0.f, 0.f, 0.f);
    for (int c = beg; c < end; c += 32) {
        int m = min(32, end - c);
        int s = 0; float vv = 0.f;
        if (lane < m) { s = g_srcs_ab[c + lane]; vv = g_vals_ab[c + lane]; }
        int j = 0;
        for (; j + 4 <= m; j += 4) {
            int s0 = __shfl_sync(0xffffffffu, s, j);
            int s1 = __shfl_sync(0xffffffffu, s, j + 1);
            int s2 = __shfl_sync(0xffffffffu, s, j + 2);
            int s3 = __shfl_sync(0xffffffffu, s, j + 3);
            float u0 = __shfl_sync(0xffffffffu, vv, j);
            float u1 = __shfl_sync(0xffffffffu, vv, j + 1);
            float u2 = __shfl_sync(0xffffffffu, vv, j + 2);
            float u3 = __shfl_sync(0xffffffffu, vv, j + 3);
            const float4 f0 = *reinterpret_cast<const float4*>(feat_A + (((size_t)s0 * VV + v) << 7) + (lane << 2));
            const float4 f1 = *reinterpret_cast<const float4*>(feat_A + (((size_t)s1 * VV + v) << 7) + (lane << 2));
            const float4 f2 = *reinterpret_cast<const float4*>(feat_A + (((size_t)s2 * VV + v) << 7) + (lane << 2));
            const float4 f3 = *reinterpret_cast<const float4*>(feat_A + (((size_t)s3 * VV + v) << 7) + (lane << 2));
            acc.x = fmaf(f0.x, u0, acc.x); acc.y = fmaf(f0.y, u0, acc.y);
            acc.z = fmaf(f0.z, u0, acc.z); acc.w = fmaf(f0.w, u0, acc.w);
            acc.x = fmaf(f1.x, u1, acc.x); acc.y = fmaf(f1.y, u1, acc.y);
            acc.z = fmaf(f1.z, u1, acc.z); acc.w = fmaf(f1.w, u1, acc.w);
            acc.x = fmaf(f2.x, u2, acc.x); acc.y = fmaf(f2.y, u2, acc.y);
            acc.z = fmaf(f2.z, u2, acc.z); acc.w = fmaf(f2.w, u2, acc.w);
            acc.x = fmaf(f3.x, u3, acc.x); acc.y = fmaf(f3.y, u3, acc.y);
            acc.z = fmaf(f3.z, u3, acc.z); acc.w = fmaf(f3.w, u3, acc.w);
        }
        for (; j < m; j++) {
            int sj = __shfl_sync(0xffffffffu, s, j);
            float vj = __shfl_sync(0xffffffffu, vv, j);
            const float4 f = *reinterpret_cast<const float4*>(feat_A + (((size_t)sj * VV + v) << 7) + (lane << 2));
            acc.x = fmaf(f.x, vj, acc.x); acc.y = fmaf(f.y, vj, acc.y);
            acc.z = fmaf(f.z, vj, acc.z); acc.w = fmaf(f.w, vj, acc.w);
        }
    }
    float sq = warp_sum(acc.x * acc.x + acc.y * acc.y + acc.z * acc.z + acc.w * acc.w);
    float inv = 1.f / fmaxf(sqrtf(sq), 1e-12f);
    *reinterpret_cast<float4*>(g_hB + (((size_t)n * VV + v) << 7) + (lane << 2)) =
        make_float4(acc.x * inv, acc.y * inv, acc.z * inv, acc.w * inv);
}

// warp per (node_A, v): h_ABA from g_hB, h_BA from feat_B — same edges, fused
__global__ void k_spmm_ba(const float* __restrict__ feat_B) {
    int w = (blockIdx.x * blockDim.x + threadIdx.x) >> 5;
    int lane = threadIdx.x & 31;
    if (w >= N_A * VV) return;
    int n = w >> 1, v = w & 1;
    int beg = g_ptr_ba[n], end = g_ptr_ba[n + 1];
    float4 a1 = make_float4(0.f, 0.f, 0.f, 0.f);
    float4 a2 = make_float4(0.f, 0.f, 0.f, 0.f);
    for (int c = beg; c < end; c += 32) {
        int m = min(32, end - c);
        int s = 0; float vv = 0.f;
        if (lane < m) { s = g_srcs_ba[c + lane]; vv = g_vals_ba[c + lane]; }
        int j = 0;
        for (; j + 2 <= m; j += 2) {
            int s0 = __shfl_sync(0xffffffffu, s, j);
            int s1 = __shfl_sync(0xffffffffu, s, j + 1);
            float u0 = __shfl_sync(0xffffffffu, vv, j);
            float u1 = __shfl_sync(0xffffffffu, vv, j + 1);
            size_t o0 = (((size_t)s0 * VV + v) << 7) + (lane << 2);
            size_t o1 = (((size_t)s1 * VV + v) << 7) + (lane << 2);
            const float4 p0 = *reinterpret_cast<const float4*>(g_hB + o0);
            const float4 q0 = *reinterpret_cast<const float4*>(feat_B + o0);
            const float4 p1 = *reinterpret_cast<const float4*>(g_hB + o1);
            const float4 q1 = *reinterpret_cast<const float4*>(feat_B + o1);
            a1.x = fmaf(p0.x, u0, a1.x); a1.y = fmaf(p0.y, u0, a1.y);
            a1.z = fmaf(p0.z, u0, a1.z); a1.w = fmaf(p0.w, u0, a1.w);
            a2.x = fmaf(q0.x, u0, a2.x); a2.y = fmaf(q0.y, u0, a2.y);
            a2.z = fmaf(q0.z, u0, a2.z); a2.w = fmaf(q0.w, u0, a2.w);
            a1.x = fmaf(p1.x, u1, a1.x); a1.y = fmaf(p1.y, u1, a1.y);
            a1.z = fmaf(p1.z, u1, a1.z); a1.w = fmaf(p1.w, u1, a1.w);
            a2.x = fmaf(q1.x, u1, a2.x); a2.y = fmaf(q1.y, u1, a2.y);
            a2.z = fmaf(q1.z, u1, a2.z); a2.w = fmaf(q1.w, u1, a2.w);
        }
        for (; j < m; j++) {
            int sj = __shfl_sync(0xffffffffu, s, j);
            float vj = __shfl_sync(0xffffffffu, vv, j);
            size_t off = (((size_t)sj * VV + v) << 7) + (lane << 2);
            const float4 f1 = *reinterpret_cast<const float4*>(g_hB + off);
            const float4 f2 = *reinterpret_cast<const float4*>(feat_B + off);
            a1.x = fmaf(f1.x, vj, a1.x); a1.y = fmaf(f1.y, vj, a1.y);
            a1.z = fmaf(f1.z, vj, a1.z); a1.w = fmaf(f1.w, vj, a1.w);
            a2.x = fmaf(f2.x, vj, a2.x); a2.y = fmaf(f2.y, vj, a2.y);
            a2.z = fmaf(f2.z, vj, a2.z); a2.w = fmaf(f2.w, vj, a2.w);
        }
    }
    size_t outoff = (((size_t)n * VV + v) << 7) + (lane << 2);
    float sq1 = warp_sum(a1.x * a1.x + a1.y * a1.y + a1.z * a1.z + a1.w * a1.w);
    float i1 = 1.f / fmaxf(sqrtf(sq1), 1e-12f);
    *reinterpret_cast<float4*>(g_hABA + outoff) =
        make_float4(a1.x * i1, a1.y * i1, a1.z * i1, a1.w * i1);
    float sq2 = warp_sum(a2.x * a2.x + a2.y * a2.y + a2.z * a2.z + a2.w * a2.w);
    float i2 = 1.f / fmaxf(sqrtf(sq2), 1e-12f);
    *reinterpret_cast<float4*>(g_hBA + outoff) =
        make_float4(a2.x * i2, a2.y * i2, a2.z * i2, a2.w * i2);
}

// ---------------- GEMM kernels (persistent, W^T in smem, 4 rows/warp, f32x2 FMA) ----------------

// proj: relu(LN(in @ W^T + b)) -> g_x[.., which, :]
__global__ void __launch_bounds__(256) k_proj(
        const float* __restrict__ Wm, const float* __restrict__ bm,
        const float* __restrict__ gm, const float* __restrict__ bem, int which) {
    extern __shared__ float sm[];
    float* sWt = sm;
    unsigned long long* sX = reinterpret_cast<unsigned long long*>(sm + DD * DD);
    for (int idx = threadIdx.x; idx < DD * DD; idx += blockDim.x) {
        int j = idx >> 7, k = idx & 127;
        sWt[k * DD + j] = Wm[idx];
    }
    int lane = threadIdx.x & 31, w = threadIdx.x >> 5;
    const float* in = which ? g_hBA : g_hABA;
    float4 b4  = *reinterpret_cast<const float4*>(bm  + (lane << 2));
    float4 g4  = *reinterpret_cast<const float4*>(gm  + (lane << 2));
    float4 be4 = *reinterpret_cast<const float4*>(bem + (lane << 2));
    __syncthreads();
    unsigned long long* xr = sX + (size_t)w * 4 * DD;
    const int NT = ROWS_H / 32;
    for (int t = blockIdx.x; t < NT; t += gridDim.x) {
        int base = t * 32 + w * 4;
#pragma unroll
        for (int r = 0; r < 4; r++) {
            const float* row = in + (size_t)(base + r) * DD;
#pragma unroll
            for (int c = 0; c < 4; c++)
                xr[r * DD + lane + 32 * c] = pk2(row[lane + 32 * c]);
        }
        __syncwarp();
        unsigned long long acc[4][2];
#pragma unroll
        for (int r = 0; r < 4; r++) { acc[r][0] = 0ull; acc[r][1] = 0ull; }
#pragma unroll 2
        for (int k = 0; k < DD; k += 2) {
            ulonglong2 w0 = *reinterpret_cast<const ulonglong2*>(sWt + k * DD + (lane << 2));
            ulonglong2 w1 = *reinterpret_cast<const ulonglong2*>(sWt + (k + 1) * DD + (lane << 2));
#pragma unroll
            for (int r = 0; r < 4; r++) {
                ulonglong2 xv = *reinterpret_cast<const ulonglong2*>(xr + r * DD + k);
                ffma2(acc[r][0], w0.x, xv.x);
                ffma2(acc[r][1], w0.y, xv.x);
                ffma2(acc[r][0], w1.x, xv.y);
                ffma2(acc[r][1], w1.y, xv.y);
            }
        }
#pragma unroll
        for (int r = 0; r < 4; r++) {
            float4 p = acc2f4(acc[r]);
            float4 tt = make_float4(p.x + b4.x, p.y + b4.y, p.z + b4.z, p.w + b4.w);
            float mu = warp_sum(tt.x + tt.y + tt.z + tt.w) * (1.f / DD);
            float4 d = make_float4(tt.x - mu, tt.y - mu, tt.z - mu, tt.w - mu);
            float var = warp_sum(d.x * d.x + d.y * d.y + d.z * d.z + d.w * d.w) * (1.f / DD);
            float rs = rsqrtf(var + 1e-5f);
            float4 o = make_float4(fmaxf(d.x * rs * g4.x + be4.x, 0.f),
                                   fmaxf(d.y * rs * g4.y + be4.y, 0.f),
                                   fmaxf(d.z * rs * g4.z + be4.z, 0.f),
                                   fmaxf(d.w * rs * g4.w + be4.w, 0.f));
            *reinterpret_cast<float4*>(
                g_x + ((size_t)(base + r) * PP + which) * DD + (lane << 2)) = o;
        }
        __syncwarp();
    }
}

// fused qkv + attention over P=2 (H=4 heads, dh=32): warp owns 4 rows = 2 (n,v) units
__global__ void __launch_bounds__(256) k_qkv_attn(const float* __restrict__ Win,
                                                  const float* __restrict__ bin_) {
    extern __shared__ float sm[];
    float* sW = sm;  // [3][128][128]: m, k, j
    unsigned long long* sX = reinterpret_cast<unsigned long long*>(sm + 3 * DD * DD);
    for (int idx = threadIdx.x; idx < 3 * DD * DD; idx += blockDim.x) {
        int m = idx >> 14;
        int rem = idx & 16383;
        int j = rem >> 7, k = rem & 127;
        sW[m * 16384 + k * DD + j] = Win[(m * DD + j) * DD + k];
    }
    int lane = threadIdx.x & 31, w = threadIdx.x >> 5;
    float4 bq = *reinterpret_cast<const float4*>(bin_ + (lane << 2));
    float4 bk = *reinterpret_cast<const float4*>(bin_ + DD + (lane << 2));
    float4 bv = *reinterpret_cast<const float4*>(bin_ + 2 * DD + (lane << 2));
    __syncthreads();
    unsigned long long* xr = sX + (size_t)w * 4 * DD;
    const float* sWq = sW;
    const float* sWk = sW + 16384;
    const float* sWv = sW + 32768;
    const float qscale = 0.17677669529663687f;  // 32^-0.5
    const int NT = ROWS_X / 32;
    for (int t = blockIdx.x; t < NT; t += gridDim.x) {
        int base = t * 32 + w * 4;
#pragma unroll
        for (int r = 0; r < 4; r++) {
            const float* row = g_x + (size_t)(base + r) * DD;
#pragma unroll
            for (int c = 0; c < 4; c++)
                xr[r * DD + lane + 32 * c] = pk2(row[lane + 32 * c]);
        }
        __syncwarp();
        unsigned long long aq[4][2], ak[4][2], av[4][2];
#pragma unroll
        for (int r = 0; r < 4; r++) {
            aq[r][0] = aq[r][1] = 0ull;
            ak[r][0] = ak[r][1] = 0ull;
            av[r][0] = av[r][1] = 0ull;
        }
#pragma unroll 2
        for (int k = 0; k < DD; k += 2) {
            ulonglong2 wq0 = *reinterpret_cast<const ulonglong2*>(sWq + k * DD + (lane << 2));
            ulonglong2 wq1 = *reinterpret_cast<const ulonglong2*>(sWq + (k + 1) * DD + (lane << 2));
            ulonglong2 wk0 = *reinterpret_cast<const ulonglong2*>(sWk + k * DD + (lane << 2));
            ulonglong2 wk1 = *reinterpret_cast<const ulonglong2*>(sWk + (k + 1) * DD + (lane << 2));
            ulonglong2 wv0 = *reinterpret_cast<const ulonglong2*>(sWv + k * DD + (lane << 2));
            ulonglong2 wv1 = *reinterpret_cast<const ulonglong2*>(sWv + (k + 1) * DD + (lane << 2));
#pragma unroll
            for (int r = 0; r < 4; r++) {
                ulonglong2 xv = *reinterpret_cast<const ulonglong2*>(xr + r * DD + k);
                ffma2(aq[r][0], wq0.x, xv.x); ffma2(aq[r][1], wq0.y, xv.x);
                ffma2(ak[r][0], wk0.x, xv.x); ffma2(ak[r][1], wk0.y, xv.x);
                ffma2(av[r][0], wv0.x, xv.x); ffma2(av[r][1], wv0.y, xv.x);
                ffma2(aq[r][0], wq1.x, xv.y); ffma2(aq[r][1], wq1.y, xv.y);
                ffma2(ak[r][0], wk1.x, xv.y); ffma2(ak[r][1], wk1.y, xv.y);
                ffma2(av[r][0], wv1.x, xv.y); ffma2(av[r][1], wv1.y, xv.y);
            }
        }
        // attention per (n,v) unit: rows (2u, 2u+1) of this warp's 4 rows
#pragma unroll
        for (int u = 0; u < 2; u++) {
            int r0 = 2 * u, r1 = 2 * u + 1;
            float4 q0 = acc2f4(aq[r0]); float4 q1 = acc2f4(aq[r1]);
            float4 k0 = acc2f4(ak[r0]); float4 k1 = acc2f4(ak[r1]);
            float4 v0 = acc2f4(av[r0]); float4 v1 = acc2f4(av[r1]);
            q0.x += bq.x; q0.y += bq.y; q0.z += bq.z; q0.w += bq.w;
            q1.x += bq.x; q1.y += bq.y; q1.z += bq.z; q1.w += bq.w;
            k0.x += bk.x; k0.y += bk.y; k0.z += bk.z; k0.w += bk.w;
            k1.x += bk.x; k1.y += bk.y; k1.z += bk.z; k1.w += bk.w;
            v0.x += bv.x; v0.y += bv.y; v0.z += bv.z; v0.w += bv.w;
            v1.x += bv.x; v1.y += bv.y; v1.z += bv.z; v1.w += bv.w;
            // per-head (8 lanes = 32 dims) dot products; scale scores by dh^-0.5
            float s00 = sum8(q0.x * k0.x + q0.y * k0.y + q0.z * k0.z + q0.w * k0.w) * qscale;
            float s01 = sum8(q0.x * k1.x + q0.y * k1.y + q0.z * k1.z + q0.w * k1.w) * qscale;
            float s10 = sum8(q1.x * k0.x + q1.y * k0.y + q1.z * k0.z + q1.w * k0.w) * qscale;
            float s11 = sum8(q1.x * k1.x + q1.y * k1.y + q1.z * k1.z + q1.w * k1.w) * qscale;
            float m0 = fmaxf(s00, s01), m1 = fmaxf(s10, s11);
            float e00 = expf(s00 - m0), e01 = expf(s01 - m0);
            float e10 = expf(s10 - m1), e11 = expf(s11 - m1);
            float i0 = 1.f / (e00 + e01), i1 = 1.f / (e10 + e11);
            float a00 = e00 * i0, a01 = e01 * i0;
            float a10 = e10 * i1, a11 = e11 * i1;
            float4 o0 = make_float4(a00 * v0.x + a01 * v1.x, a00 * v0.y + a01 * v1.y,
                                    a00 * v0.z + a01 * v1.z, a00 * v0.w + a01 * v1.w);
            float4 o1 = make_float4(a10 * v0.x + a11 * v1.x, a10 * v0.y + a11 * v1.y,
                                    a10 * v0.z + a11 * v1.z, a10 * v0.w + a11 * v1.w);
            *reinterpret_cast<float4*>(g_o + (size_t)(base + r0) * DD + (lane << 2)) = o0;
            *reinterpret_cast<float4*>(g_o + (size_t)(base + r1) * DD + (lane << 2)) = o1;
        }
        __syncwarp();
    }
}

// final: attn = g_o @ Wout^T + bout; t = LN(attn + g_x); y = mean over P -> d_out
__global__ void __launch_bounds__(256) k_out(
        const float* __restrict__ Wm, const float* __restrict__ bm,
        const float* __restrict__ gm, const float* __restrict__ bem,
        float* __restrict__ outp) {
    extern __shared__ float sm[];
    float* sWt = sm;
    unsigned long long* sX = reinterpret_cast<unsigned long long*>(sm + DD * DD);
    for (int idx = threadIdx.x; idx < DD * DD; idx += blockDim.x) {
        int j = idx >> 7, k = idx & 127;
        sWt[k * DD + j] = Wm[idx];
    }
    int lane = threadIdx.x & 31, w = threadIdx.x >> 5;
    float4 b4  = *reinterpret_cast<const float4*>(bm  + (lane << 2));
    float4 g4  = *reinterpret_cast<const float4*>(gm  + (lane << 2));
    float4 be4 = *reinterpret_cast<const float4*>(bem + (lane << 2));
    __syncthreads();
    unsigned long long* xr = sX + (size_t)w * 4 * DD;
    const int NT = ROWS_X / 32;
    for (int t = blockIdx.x; t < NT; t += gridDim.x) {
        int base = t * 32 + w * 4;  // 4 rows = 2 (n,v) units
#pragma unroll
        for (int r = 0; r < 4; r++) {
            const float* row = g_o + (size_t)(base + r) * DD;
#pragma unroll
            for (int c = 0; c < 4; c++)
                xr[r * DD + lane + 32 * c] = pk2(row[lane + 32 * c]);
        }
        __syncwarp();
        unsigned long long acc[4][2];
#pragma unroll
        for (int r = 0; r < 4; r++) { acc[r][0] = 0ull; acc[r][1] = 0ull; }
#pragma unroll 2
        for (int k = 0; k < DD; k += 2) {
            ulonglong2 w0 = *reinterpret_cast<const ulonglong2*>(sWt + k * DD + (lane << 2));
            ulonglong2 w1 = *reinterpret_cast<const ulonglong2*>(sWt + (k + 1) * DD + (lane << 2));
#pragma unroll
            for (int r = 0; r < 4; r++) {
                ulonglong2 xv = *reinterpret_cast<const ulonglong2*>(xr + r * DD + k);
                ffma2(acc[r][0], w0.x, xv.x);
                ffma2(acc[r][1], w0.y, xv.x);
                ffma2(acc[r][0], w1.x, xv.y);
                ffma2(acc[r][1], w1.y, xv.y);
            }
        }
        float4 ys0 = make_float4(0.f, 0.f, 0.f, 0.f);
        float4 ys1 = make_float4(0.f, 0.f, 0.f, 0.f);
#pragma unroll
        for (int r = 0; r < 4; r++) {
            float4 p = acc2f4(acc[r]);
            float4 x4 = *reinterpret_cast<const float4*>(
                g_x + (size_t)(base + r) * DD + (lane << 2));
            float4 tt = make_float4(p.x + b4.x + x4.x, p.y + b4.y + x4.y,
                                    p.z + b4.z + x4.z, p.w + b4.w + x4.w);
            float mu = warp_sum(tt.x + tt.y + tt.z + tt.w) * (1.f / DD);
            float4 d = make_float4(tt.x - mu, tt.y - mu, tt.z - mu, tt.w - mu);
            float var = warp_sum(d.x * d.x + d.y * d.y + d.z * d.z + d.w * d.w) * (1.f / DD);
            float rs = rsqrtf(var + 1e-5f);
            float4 tn = make_float4(d.x * rs * g4.x + be4.x, d.y * rs * g4.y + be4.y,
                                    d.z * rs * g4.z + be4.z, d.w * rs * g4.w + be4.w);
            if (r < 2) {
                ys0.x += tn.x; ys0.y += tn.y; ys0.z += tn.z; ys0.w += tn.w;
            } else {
                ys1.x += tn.x; ys1.y += tn.y; ys1.z += tn.z; ys1.w += tn.w;
            }
        }
        int u0 = base >> 1;
        *reinterpret_cast<float4*>(outp + (size_t)u0 * DD + (lane << 2)) =
            make_float4(ys0.x * 0.5f, ys0.y * 0.5f, ys0.z * 0.5f, ys0.w * 0.5f);
        *reinterpret_cast<float4*>(outp + (size_t)(u0 + 1) * DD + (lane << 2)) =
            make_float4(ys1.x * 0.5f, ys1.y * 0.5f, ys1.z * 0.5f, ys1.w * 0.5f);
        __syncwarp();
    }
}

// ---------------- launch ----------------
extern "C" void kernel_launch(void* const* d_in, const int* in_sizes, int n_in,
                              void* d_out, int out_size) {
    (void)in_sizes; (void)n_in; (void)out_size;
    const float* feat_A = (const float*)d_in[0];
    const float* feat_B = (const float*)d_in[1];
    const int*   src_ab = (const int*)d_in[2];
    const int*   dst_ab = (const int*)d_in[3];
    const float* val_ab = (const float*)d_in[4];
    const int*   src_ba = (const int*)d_in[5];
    const int*   dst_ba = (const int*)d_in[6];
    const float* val_ba = (const float*)d_in[7];
    const float* W1  = (const float*)d_in[8];
    const float* b1  = (const float*)d_in[9];
    const float* g1  = (const float*)d_in[10];
    const float* be1 = (const float*)d_in[11];
    const float* W2  = (const float*)d_in[12];
    const float* b2  = (const float*)d_in[13];
    const float* g2  = (const float*)d_in[14];
    const float* be2 = (const float*)d_in[15];
    const float* Win  = (const float*)d_in[16];
    const float* bin_ = (const float*)d_in[17];
    const float* Wout = (const float*)d_in[18];
    const float* bout = (const float*)d_in[19];
    const float* lng  = (const float*)d_in[20];
    const float* lnb  = (const float*)d_in[21];
    float* outp = (float*)d_out;

    cudaFuncSetAttribute(k_proj,     cudaFuncAttributeMaxDynamicSharedMemorySize, SMEM_PROJ);
    cudaFuncSetAttribute(k_qkv_attn, cudaFuncAttributeMaxDynamicSharedMemorySize, SMEM_QKV);
    cudaFuncSetAttribute(k_out,      cudaFuncAttributeMaxDynamicSharedMemorySize, SMEM_PROJ);

    // CSR build (dst-grouped), with CSR-sorted src/val
    k_zero_cnt<<<118, 256>>>();
    k_hist<<<1875, 256>>>(dst_ab, dst_ba);
    k_scan<<<2, 1024>>>();
    k_zero_cnt<<<118, 256>>>();
    k_scatter<<<1875, 256>>>(dst_ab, src_ab, val_ab, dst_ba, src_ba, val_ba);

    // spmm + fused l2norm
    k_spmm_ab<<<7500, 256>>>(feat_A);
    k_spmm_ba<<<7500, 256>>>(feat_B);

    // proj -> x (stacked), persistent grids
    k_proj<<<608, 256, SMEM_PROJ>>>(W1, b1, g1, be1, 0);
    k_proj<<<608, 256, SMEM_PROJ>>>(W2, b2, g2, be2, 1);

    // fused qkv + attention -> g_o
    k_qkv_attn<<<456, 256, SMEM_QKV>>>(Win, bin_);

    // Wout + residual + LN + mean over P
    k_out<<<608, 256, SMEM_PROJ>>>(Wout, bout, lng, lnb, outp);
}

// round 6
// speedup vs baseline: 1.4425x; 1.1465x over previous
#include <cuda_runtime.h>

// ---------------- problem constants ----------------
#define N_A   30000
#define N_B   30000
#define VV    2
#define DD    128
#define EE    480000
#define PP    2

#define ROWS_H 60000    // N_A*V   (also N_B*V)
#define ROWS_X 120000   // N_A*V*P

// proj/out kernels: W^T (64KB) + x stage (8 warps * 8 rows * 128 ull = 64KB)
#define SMEM_PROJ (DD*DD*4 + 8*8*DD*8)           // 131072 -> 1 block/SM
// qkv kernel: 3x W^T (192KB) + x stage (8 warps * 4 rows * 128 ull = 32KB)
#define SMEM_QKV  (3*DD*DD*4 + 8*4*DD*8)         // 229376 -> 1 block/SM

#define GRID_GEMM 148   // one resident block per SM (persistent)

// ---------------- scratch (device globals; no allocation allowed) ----------------
__device__ int g_cnt_ab[N_B];
__device__ int g_cnt_ba[N_A];
__device__ int g_ptr_ab[N_B + 1];
__device__ int g_ptr_ba[N_A + 1];
__device__ int   g_srcs_ab[EE];   // CSR-sorted src
__device__ float g_vals_ab[EE];   // CSR-sorted val
__device__ int   g_srcs_ba[EE];
__device__ float g_vals_ba[EE];

__device__ float g_hB  [(size_t)N_B * VV * DD];   // l2norm(spmm(feat_A)) at B
__device__ float g_hABA[(size_t)N_A * VV * DD];   // l2norm(spmm(g_hB)) at A
__device__ float g_hBA [(size_t)N_A * VV * DD];   // l2norm(spmm(feat_B)) at A
__device__ float g_x[(size_t)ROWS_X * DD];        // stacked [n][v][p][d]
__device__ float g_o[(size_t)ROWS_X * DD];        // attention output

// ---------------- helpers ----------------
static __device__ __forceinline__ float warp_sum(float v) {
#pragma unroll
    for (int o = 16; o > 0; o >>= 1) v += __shfl_xor_sync(0xffffffffu, v, o);
    return v;
}
static __device__ __forceinline__ float sum8(float v) {
    v += __shfl_xor_sync(0xffffffffu, v, 1);
    v += __shfl_xor_sync(0xffffffffu, v, 2);
    v += __shfl_xor_sync(0xffffffffu, v, 4);
    return v;
}

// packed f32x2 FMA (B300 FFMA2 path: 2x scalar FFMA throughput)
static __device__ __forceinline__ unsigned long long pk2(float x) {
    unsigned long long r;
    asm("mov.b64 %0, {%1, %1};" : "=l"(r) : "f"(x));
    return r;
}
static __device__ __forceinline__ void ffma2(unsigned long long& d,
                                             unsigned long long a,
                                             unsigned long long b) {
    asm("fma.rn.f32x2 %0, %1, %2, %0;" : "+l"(d) : "l"(a), "l"(b));
}
static __device__ __forceinline__ float2 upk2(unsigned long long a) {
    float2 f;
    asm("mov.b64 {%0, %1}, %2;" : "=f"(f.x), "=f"(f.y) : "l"(a));
    return f;
}
static __device__ __forceinline__ float4 acc2f4(const unsigned long long* a) {
    float2 p0 = upk2(a[0]), p1 = upk2(a[1]);
    return make_float4(p0.x, p0.y, p1.x, p1.y);
}

// ---------------- CSR build ----------------
__global__ void k_zero_cnt() {
    int i = blockIdx.x * blockDim.x + threadIdx.x;
    if (i < N_B) g_cnt_ab[i] = 0;
    if (i < N_A) g_cnt_ba[i] = 0;
}

__global__ void k_hist(const int* __restrict__ dst_ab, const int* __restrict__ dst_ba) {
    int e = blockIdx.x * blockDim.x + threadIdx.x;
    if (e < EE) {
        atomicAdd(&g_cnt_ab[dst_ab[e]], 1);
        atomicAdd(&g_cnt_ba[dst_ba[e]], 1);
    }
}

__global__ void k_scan() {
    __shared__ int ssum[1024];
    const int n = N_A;  // both 30000
    int* cnt = (blockIdx.x == 0) ? g_cnt_ab : g_cnt_ba;
    int* ptr = (blockIdx.x == 0) ? g_ptr_ab : g_ptr_ba;
    int t = threadIdx.x;
    const int chunk = (n + 1023) / 1024;
    int b0 = t * chunk;
    int b1 = min(b0 + chunk, n);
    int s = 0;
    for (int i = b0; i < b1; i++) s += cnt[i];
    ssum[t] = s;
    __syncthreads();
#pragma unroll
    for (int off = 1; off < 1024; off <<= 1) {
        int v = (t >= off) ? ssum[t - off] : 0;
        __syncthreads();
        ssum[t] += v;
        __syncthreads();
    }
    int run = (t == 0) ? 0 : ssum[t - 1];
    for (int i = b0; i < b1; i++) { ptr[i] = run; run += cnt[i]; }
    if (t == 1023) ptr[n] = ssum[1023];
}

__global__ void k_scatter(const int* __restrict__ dst_ab, const int* __restrict__ src_ab,
                          const float* __restrict__ val_ab,
                          const int* __restrict__ dst_ba, const int* __restrict__ src_ba,
                          const float* __restrict__ val_ba) {
    int e = blockIdx.x * blockDim.x + threadIdx.x;
    if (e < EE) {
        int d = dst_ab[e];
        int p = g_ptr_ab[d] + atomicAdd(&g_cnt_ab[d], 1);
        g_srcs_ab[p] = src_ab[e];
        g_vals_ab[p] = val_ab[e];
        d = dst_ba[e];
        p = g_ptr_ba[d] + atomicAdd(&g_cnt_ba[d], 1);
        g_srcs_ba[p] = src_ba[e];
        g_vals_ba[p] = val_ba[e];
    }
}

// ---------------- spmm + fused l2norm ----------------
// warp per (node_B, v): h_B = l2norm( sum_e feat_A[src]*val )
__global__ void k_spmm_ab(const float* __restrict__ feat_A) {
    int w = (blockIdx.x * blockDim.x + threadIdx.x) >> 5;
    int lane = threadIdx.x & 31;
    if (w >= N_B * VV) return;
    int n = w >> 1, v = w & 1;
    int beg = g_ptr_ab[n], end = g_ptr_ab[n + 1];
    float4 acc = make_float4(0.f, 0.f, 0.f, 0.f);
    for (int c = beg; c < end; c += 32) {
        int m = min(32, end - c);
        int s = 0; float vv = 0.f;
        if (lane < m) { s = g_srcs_ab[c + lane]; vv = g_vals_ab[c + lane]; }
        int j = 0;
        for (; j + 4 <= m; j += 4) {
            int s0 = __shfl_sync(0xffffffffu, s, j);
            int s1 = __shfl_sync(0xffffffffu, s, j + 1);
            int s2 = __shfl_sync(0xffffffffu, s, j + 2);
            int s3 = __shfl_sync(0xffffffffu, s, j + 3);
            float u0 = __shfl_sync(0xffffffffu, vv, j);
            float u1 = __shfl_sync(0xffffffffu, vv, j + 1);
            float u2 = __shfl_sync(0xffffffffu, vv, j + 2);
            float u3 = __shfl_sync(0xffffffffu, vv, j + 3);
            const float4 f0 = *reinterpret_cast<const float4*>(feat_A + (((size_t)s0 * VV + v) << 7) + (lane << 2));
            const float4 f1 = *reinterpret_cast<const float4*>(feat_A + (((size_t)s1 * VV + v) << 7) + (lane << 2));
            const float4 f2 = *reinterpret_cast<const float4*>(feat_A + (((size_t)s2 * VV + v) << 7) + (lane << 2));
            const float4 f3 = *reinterpret_cast<const float4*>(feat_A + (((size_t)s3 * VV + v) << 7) + (lane << 2));
            acc.x = fmaf(f0.x, u0, acc.x); acc.y = fmaf(f0.y, u0, acc.y);
            acc.z = fmaf(f0.z, u0, acc.z); acc.w = fmaf(f0.w, u0, acc.w);
            acc.x = fmaf(f1.x, u1, acc.x); acc.y = fmaf(f1.y, u1, acc.y);
            acc.z = fmaf(f1.z, u1, acc.z); acc.w = fmaf(f1.w, u1, acc.w);
            acc.x = fmaf(f2.x, u2, acc.x); acc.y = fmaf(f2.y, u2, acc.y);
            acc.z = fmaf(f2.z, u2, acc.z); acc.w = fmaf(f2.w, u2, acc.w);
            acc.x = fmaf(f3.x, u3, acc.x); acc.y = fmaf(f3.y, u3, acc.y);
            acc.z = fmaf(f3.z, u3, acc.z); acc.w = fmaf(f3.w, u3, acc.w);
        }
        for (; j < m; j++) {
            int sj = __shfl_sync(0xffffffffu, s, j);
            float vj = __shfl_sync(0xffffffffu, vv, j);
            const float4 f = *reinterpret_cast<const float4*>(feat_A + (((size_t)sj * VV + v) << 7) + (lane << 2));
            acc.x = fmaf(f.x, vj, acc.x); acc.y = fmaf(f.y, vj, acc.y);
            acc.z = fmaf(f.z, vj, acc.z); acc.w = fmaf(f.w, vj, acc.w);
        }
    }
    float sq = warp_sum(acc.x * acc.x + acc.y * acc.y + acc.z * acc.z + acc.w * acc.w);
    float inv = 1.f / fmaxf(sqrtf(sq), 1e-12f);
    *reinterpret_cast<float4*>(g_hB + (((size_t)n * VV + v) << 7) + (lane << 2)) =
        make_float4(acc.x * inv, acc.y * inv, acc.z * inv, acc.w * inv);
}

// warp per (node_A, v): h_ABA from g_hB, h_BA from feat_B — same edges, fused
__global__ void k_spmm_ba(const float* __restrict__ feat_B) {
    int w = (blockIdx.x * blockDim.x + threadIdx.x) >> 5;
    int lane = threadIdx.x & 31;
    if (w >= N_A * VV) return;
    int n = w >> 1, v = w & 1;
    int beg = g_ptr_ba[n], end = g_ptr_ba[n + 1];
    float4 a1 = make_float4(0.f, 0.f, 0.f, 0.f);
    float4 a2 = make_float4(0.f, 0.f, 0.f, 0.f);
    for (int c = beg; c < end; c += 32) {
        int m = min(32, end - c);
        int s = 0; float vv = 0.f;
        if (lane < m) { s = g_srcs_ba[c + lane]; vv = g_vals_ba[c + lane]; }
        int j = 0;
        for (; j + 2 <= m; j += 2) {
            int s0 = __shfl_sync(0xffffffffu, s, j);
            int s1 = __shfl_sync(0xffffffffu, s, j + 1);
            float u0 = __shfl_sync(0xffffffffu, vv, j);
            float u1 = __shfl_sync(0xffffffffu, vv, j + 1);
            size_t o0 = (((size_t)s0 * VV + v) << 7) + (lane << 2);
            size_t o1 = (((size_t)s1 * VV + v) << 7) + (lane << 2);
            const float4 p0 = *reinterpret_cast<const float4*>(g_hB + o0);
            const float4 q0 = *reinterpret_cast<const float4*>(feat_B + o0);
            const float4 p1 = *reinterpret_cast<const float4*>(g_hB + o1);
            const float4 q1 = *reinterpret_cast<const float4*>(feat_B + o1);
            a1.x = fmaf(p0.x, u0, a1.x); a1.y = fmaf(p0.y, u0, a1.y);
            a1.z = fmaf(p0.z, u0, a1.z); a1.w = fmaf(p0.w, u0, a1.w);
            a2.x = fmaf(q0.x, u0, a2.x); a2.y = fmaf(q0.y, u0, a2.y);
            a2.z = fmaf(q0.z, u0, a2.z); a2.w = fmaf(q0.w, u0, a2.w);
            a1.x = fmaf(p1.x, u1, a1.x); a1.y = fmaf(p1.y, u1, a1.y);
            a1.z = fmaf(p1.z, u1, a1.z); a1.w = fmaf(p1.w, u1, a1.w);
            a2.x = fmaf(q1.x, u1, a2.x); a2.y = fmaf(q1.y, u1, a2.y);
            a2.z = fmaf(q1.z, u1, a2.z); a2.w = fmaf(q1.w, u1, a2.w);
        }
        for (; j < m; j++) {
            int sj = __shfl_sync(0xffffffffu, s, j);
            float vj = __shfl_sync(0xffffffffu, vv, j);
            size_t off = (((size_t)sj * VV + v) << 7) + (lane << 2);
            const float4 f1 = *reinterpret_cast<const float4*>(g_hB + off);
            const float4 f2 = *reinterpret_cast<const float4*>(feat_B + off);
            a1.x = fmaf(f1.x, vj, a1.x); a1.y = fmaf(f1.y, vj, a1.y);
            a1.z = fmaf(f1.z, vj, a1.z); a1.w = fmaf(f1.w, vj, a1.w);
            a2.x = fmaf(f2.x, vj, a2.x); a2.y = fmaf(f2.y, vj, a2.y);
            a2.z = fmaf(f2.z, vj, a2.z); a2.w = fmaf(f2.w, vj, a2.w);
        }
    }
    size_t outoff = (((size_t)n * VV + v) << 7) + (lane << 2);
    float sq1 = warp_sum(a1.x * a1.x + a1.y * a1.y + a1.z * a1.z + a1.w * a1.w);
    float i1 = 1.f / fmaxf(sqrtf(sq1), 1e-12f);
    *reinterpret_cast<float4*>(g_hABA + outoff) =
        make_float4(a1.x * i1, a1.y * i1, a1.z * i1, a1.w * i1);
    float sq2 = warp_sum(a2.x * a2.x + a2.y * a2.y + a2.z * a2.z + a2.w * a2.w);
    float i2 = 1.f / fmaxf(sqrtf(sq2), 1e-12f);
    *reinterpret_cast<float4*>(g_hBA + outoff) =
        make_float4(a2.x * i2, a2.y * i2, a2.z * i2, a2.w * i2);
}

// ---------------- GEMM kernels (persistent warp-stride, W^T in smem, f32x2 FMA) ----------------

// proj: relu(LN(in @ W^T + b)) -> g_x[.., which, :]   R=8 rows/warp
__global__ void __launch_bounds__(256) k_proj(
        const float* __restrict__ Wm, const float* __restrict__ bm,
        const float* __restrict__ gm, const float* __restrict__ bem, int which) {
    extern __shared__ float sm[];
    float* sWt = sm;
    unsigned long long* sX = reinterpret_cast<unsigned long long*>(sm + DD * DD);
    for (int idx = threadIdx.x; idx < DD * DD; idx += blockDim.x) {
        int j = idx >> 7, k = idx & 127;
        sWt[k * DD + j] = Wm[idx];
    }
    int lane = threadIdx.x & 31, w = threadIdx.x >> 5;
    const float* in = which ? g_hBA : g_hABA;
    float4 b4  = *reinterpret_cast<const float4*>(bm  + (lane << 2));
    float4 g4  = *reinterpret_cast<const float4*>(gm  + (lane << 2));
    float4 be4 = *reinterpret_cast<const float4*>(bem + (lane << 2));
    __syncthreads();
    unsigned long long* xr = sX + (size_t)w * 8 * DD;
    const int NT = ROWS_H / 8;                 // 7500 tiles of 8 rows
    const int TW = GRID_GEMM * 8;              // total warps
    int gw = blockIdx.x * 8 + w;
    for (int t = gw; t < NT; t += TW) {
        int base = t * 8;
#pragma unroll
        for (int r = 0; r < 8; r++) {
            const float* row = in + (size_t)(base + r) * DD;
#pragma unroll
            for (int c = 0; c < 4; c++)
                xr[r * DD + lane + 32 * c] = pk2(row[lane + 32 * c]);
        }
        __syncwarp();
        unsigned long long acc[8][2];
#pragma unroll
        for (int r = 0; r < 8; r++) { acc[r][0] = 0ull; acc[r][1] = 0ull; }
#pragma unroll 2
        for (int k = 0; k < DD; k += 2) {
            ulonglong2 w0 = *reinterpret_cast<const ulonglong2*>(sWt + k * DD + (lane << 2));
            ulonglong2 w1 = *reinterpret_cast<const ulonglong2*>(sWt + (k + 1) * DD + (lane << 2));
#pragma unroll
            for (int r = 0; r < 8; r++) {
                ulonglong2 xv = *reinterpret_cast<const ulonglong2*>(xr + r * DD + k);
                ffma2(acc[r][0], w0.x, xv.x);
                ffma2(acc[r][1], w0.y, xv.x);
                ffma2(acc[r][0], w1.x, xv.y);
                ffma2(acc[r][1], w1.y, xv.y);
            }
        }
#pragma unroll
        for (int r = 0; r < 8; r++) {
            float4 p = acc2f4(acc[r]);
            float4 tt = make_float4(p.x + b4.x, p.y + b4.y, p.z + b4.z, p.w + b4.w);
            float mu = warp_sum(tt.x + tt.y + tt.z + tt.w) * (1.f / DD);
            float4 d = make_float4(tt.x - mu, tt.y - mu, tt.z - mu, tt.w - mu);
            float var = warp_sum(d.x * d.x + d.y * d.y + d.z * d.z + d.w * d.w) * (1.f / DD);
            float rs = rsqrtf(var + 1e-5f);
            float4 o = make_float4(fmaxf(d.x * rs * g4.x + be4.x, 0.f),
                                   fmaxf(d.y * rs * g4.y + be4.y, 0.f),
                                   fmaxf(d.z * rs * g4.z + be4.z, 0.f),
                                   fmaxf(d.w * rs * g4.w + be4.w, 0.f));
            *reinterpret_cast<float4*>(
                g_x + ((size_t)(base + r) * PP + which) * DD + (lane << 2)) = o;
        }
        __syncwarp();
    }
}

// fused qkv + attention over P=2 (H=4 heads, dh=32): warp owns 4 rows = 2 (n,v) units
__global__ void __launch_bounds__(256) k_qkv_attn(const float* __restrict__ Win,
                                                  const float* __restrict__ bin_) {
    extern __shared__ float sm[];
    float* sW = sm;  // [3][128][128]: m, k, j
    unsigned long long* sX = reinterpret_cast<unsigned long long*>(sm + 3 * DD * DD);
    for (int idx = threadIdx.x; idx < 3 * DD * DD; idx += blockDim.x) {
        int m = idx >> 14;
        int rem = idx & 16383;
        int j = rem >> 7, k = rem & 127;
        sW[m * 16384 + k * DD + j] = Win[(m * DD + j) * DD + k];
    }
    int lane = threadIdx.x & 31, w = threadIdx.x >> 5;
    float4 bq = *reinterpret_cast<const float4*>(bin_ + (lane << 2));
    float4 bk = *reinterpret_cast<const float4*>(bin_ + DD + (lane << 2));
    float4 bv = *reinterpret_cast<const float4*>(bin_ + 2 * DD + (lane << 2));
    __syncthreads();
    unsigned long long* xr = sX + (size_t)w * 4 * DD;
    const float* sWq = sW;
    const float* sWk = sW + 16384;
    const float* sWv = sW + 32768;
    const float qscale = 0.17677669529663687f;  // 32^-0.5
    const int NT = ROWS_X / 32;                 // 3750 block-tiles of 32 rows
    // warp-stride over 4-row tiles
    const int NWT = ROWS_X / 4;                 // 30000 warp-tiles
    const int TW = GRID_GEMM * 8;
    int gw = blockIdx.x * 8 + w;
    (void)NT;
    for (int t = gw; t < NWT; t += TW) {
        int base = t * 4;
#pragma unroll
        for (int r = 0; r < 4; r++) {
            const float* row = g_x + (size_t)(base + r) * DD;
#pragma unroll
            for (int c = 0; c < 4; c++)
                xr[r * DD + lane + 32 * c] = pk2(row[lane + 32 * c]);
        }
        __syncwarp();
        unsigned long long aq[4][2], ak[4][2], av[4][2];
#pragma unroll
        for (int r = 0; r < 4; r++) {
            aq[r][0] = aq[r][1] = 0ull;
            ak[r][0] = ak[r][1] = 0ull;
            av[r][0] = av[r][1] = 0ull;
        }
#pragma unroll 2
        for (int k = 0; k < DD; k += 2) {
            ulonglong2 wq0 = *reinterpret_cast<const ulonglong2*>(sWq + k * DD + (lane << 2));
            ulonglong2 wq1 = *reinterpret_cast<const ulonglong2*>(sWq + (k + 1) * DD + (lane << 2));
            ulonglong2 wk0 = *reinterpret_cast<const ulonglong2*>(sWk + k * DD + (lane << 2));
            ulonglong2 wk1 = *reinterpret_cast<const ulonglong2*>(sWk + (k + 1) * DD + (lane << 2));
            ulonglong2 wv0 = *reinterpret_cast<const ulonglong2*>(sWv + k * DD + (lane << 2));
            ulonglong2 wv1 = *reinterpret_cast<const ulonglong2*>(sWv + (k + 1) * DD + (lane << 2));
#pragma unroll
            for (int r = 0; r < 4; r++) {
                ulonglong2 xv = *reinterpret_cast<const ulonglong2*>(xr + r * DD + k);
                ffma2(aq[r][0], wq0.x, xv.x); ffma2(aq[r][1], wq0.y, xv.x);
                ffma2(ak[r][0], wk0.x, xv.x); ffma2(ak[r][1], wk0.y, xv.x);
                ffma2(av[r][0], wv0.x, xv.x); ffma2(av[r][1], wv0.y, xv.x);
                ffma2(aq[r][0], wq1.x, xv.y); ffma2(aq[r][1], wq1.y, xv.y);
                ffma2(ak[r][0], wk1.x, xv.y); ffma2(ak[r][1], wk1.y, xv.y);
                ffma2(av[r][0], wv1.x, xv.y); ffma2(av[r][1], wv1.y, xv.y);
            }
        }
        // attention per (n,v) unit: rows (2u, 2u+1) of this warp's 4 rows
#pragma unroll
        for (int u = 0; u < 2; u++) {
            int r0 = 2 * u, r1 = 2 * u + 1;
            float4 q0 = acc2f4(aq[r0]); float4 q1 = acc2f4(aq[r1]);
            float4 k0 = acc2f4(ak[r0]); float4 k1 = acc2f4(ak[r1]);
            float4 v0 = acc2f4(av[r0]); float4 v1 = acc2f4(av[r1]);
            q0.x += bq.x; q0.y += bq.y; q0.z += bq.z; q0.w += bq.w;
            q1.x += bq.x; q1.y += bq.y; q1.z += bq.z; q1.w += bq.w;
            k0.x += bk.x; k0.y += bk.y; k0.z += bk.z; k0.w += bk.w;
            k1.x += bk.x; k1.y += bk.y; k1.z += bk.z; k1.w += bk.w;
            v0.x += bv.x; v0.y += bv.y; v0.z += bv.z; v0.w += bv.w;
            v1.x += bv.x; v1.y += bv.y; v1.z += bv.z; v1.w += bv.w;
            float s00 = sum8(q0.x * k0.x + q0.y * k0.y + q0.z * k0.z + q0.w * k0.w) * qscale;
            float s01 = sum8(q0.x * k1.x + q0.y * k1.y + q0.z * k1.z + q0.w * k1.w) * qscale;
            float s10 = sum8(q1.x * k0.x + q1.y * k0.y + q1.z * k0.z + q1.w * k0.w) * qscale;
            float s11 = sum8(q1.x * k1.x + q1.y * k1.y + q1.z * k1.z + q1.w * k1.w) * qscale;
            float m0 = fmaxf(s00, s01), m1 = fmaxf(s10, s11);
            float e00 = expf(s00 - m0), e01 = expf(s01 - m0);
            float e10 = expf(s10 - m1), e11 = expf(s11 - m1);
            float i0 = 1.f / (e00 + e01), i1 = 1.f / (e10 + e11);
            float a00 = e00 * i0, a01 = e01 * i0;
            float a10 = e10 * i1, a11 = e11 * i1;
            float4 o0 = make_float4(a00 * v0.x + a01 * v1.x, a00 * v0.y + a01 * v1.y,
                                    a00 * v0.z + a01 * v1.z, a00 * v0.w + a01 * v1.w);
            float4 o1 = make_float4(a10 * v0.x + a11 * v1.x, a10 * v0.y + a11 * v1.y,
                                    a10 * v0.z + a11 * v1.z, a10 * v0.w + a11 * v1.w);
            *reinterpret_cast<float4*>(g_o + (size_t)(base + r0) * DD + (lane << 2)) = o0;
            *reinterpret_cast<float4*>(g_o + (size_t)(base + r1) * DD + (lane << 2)) = o1;
        }
        __syncwarp();
    }
}

// final: attn = g_o @ Wout^T + bout; t = LN(attn + g_x); y = mean over P -> d_out
// R=8 rows/warp (= 4 (n,v) units)
__global__ void __launch_bounds__(256) k_out(
        const float* __restrict__ Wm, const float* __restrict__ bm,
        const float* __restrict__ gm, const float* __restrict__ bem,
        float* __restrict__ outp) {
    extern __shared__ float sm[];
    float* sWt = sm;
    unsigned long long* sX = reinterpret_cast<unsigned long long*>(sm + DD * DD);
    for (int idx = threadIdx.x; idx < DD * DD; idx += blockDim.x) {
        int j = idx >> 7, k = idx & 127;
        sWt[k * DD + j] = Wm[idx];
    }
    int lane = threadIdx.x & 31, w = threadIdx.x >> 5;
    float4 b4  = *reinterpret_cast<const float4*>(bm  + (lane << 2));
    float4 g4  = *reinterpret_cast<const float4*>(gm  + (lane << 2));
    float4 be4 = *reinterpret_cast<const float4*>(bem + (lane << 2));
    __syncthreads();
    unsigned long long* xr = sX + (size_t)w * 8 * DD;
    const int NT = ROWS_X / 8;                 // 15000 tiles of 8 rows
    const int TW = GRID_GEMM * 8;
    int gw = blockIdx.x * 8 + w;
    for (int t = gw; t < NT; t += TW) {
        int base = t * 8;  // 8 rows = 4 (n,v) units
#pragma unroll
        for (int r = 0; r < 8; r++) {
            const float* row = g_o + (size_t)(base + r) * DD;
#pragma unroll
            for (int c = 0; c < 4; c++)
                xr[r * DD + lane + 32 * c] = pk2(row[lane + 32 * c]);
        }
        __syncwarp();
        unsigned long long acc[8][2];
#pragma unroll
        for (int r = 0; r < 8; r++) { acc[r][0] = 0ull; acc[r][1] = 0ull; }
#pragma unroll 2
        for (int k = 0; k < DD; k += 2) {
            ulonglong2 w0 = *reinterpret_cast<const ulonglong2*>(sWt + k * DD + (lane << 2));
            ulonglong2 w1 = *reinterpret_cast<const ulonglong2*>(sWt + (k + 1) * DD + (lane << 2));
#pragma unroll
            for (int r = 0; r < 8; r++) {
                ulonglong2 xv = *reinterpret_cast<const ulonglong2*>(xr + r * DD + k);
                ffma2(acc[r][0], w0.x, xv.x);
                ffma2(acc[r][1], w0.y, xv.x);
                ffma2(acc[r][0], w1.x, xv.y);
                ffma2(acc[r][1], w1.y, xv.y);
            }
        }
        float4 ys[4];
#pragma unroll
        for (int u = 0; u < 4; u++) ys[u] = make_float4(0.f, 0.f, 0.f, 0.f);
#pragma unroll
        for (int r = 0; r < 8; r++) {
            float4 p = acc2f4(acc[r]);
            float4 x4 = *reinterpret_cast<const float4*>(
                g_x + (size_t)(base + r) * DD + (lane << 2));
            float4 tt = make_float4(p.x + b4.x + x4.x, p.y + b4.y + x4.y,
                                    p.z + b4.z + x4.z, p.w + b4.w + x4.w);
            float mu = warp_sum(tt.x + tt.y + tt.z + tt.w) * (1.f / DD);
            float4 d = make_float4(tt.x - mu, tt.y - mu, tt.z - mu, tt.w - mu);
            float var = warp_sum(d.x * d.x + d.y * d.y + d.z * d.z + d.w * d.w) * (1.f / DD);
            float rs = rsqrtf(var + 1e-5f);
            int u = r >> 1;
            ys[u].x += d.x * rs * g4.x + be4.x;
            ys[u].y += d.y * rs * g4.y + be4.y;
            ys[u].z += d.z * rs * g4.z + be4.z;
            ys[u].w += d.w * rs * g4.w + be4.w;
        }
        int u0 = base >> 1;
#pragma unroll
        for (int u = 0; u < 4; u++) {
            *reinterpret_cast<float4*>(outp + (size_t)(u0 + u) * DD + (lane << 2)) =
                make_float4(ys[u].x * 0.5f, ys[u].y * 0.5f, ys[u].z * 0.5f, ys[u].w * 0.5f);
        }
        __syncwarp();
    }
}

// ---------------- launch ----------------
extern "C" void kernel_launch(void* const* d_in, const int* in_sizes, int n_in,
                              void* d_out, int out_size) {
    (void)in_sizes; (void)n_in; (void)out_size;
    const float* feat_A = (const float*)d_in[0];
    const float* feat_B = (const float*)d_in[1];
    const int*   src_ab = (const int*)d_in[2];
    const int*   dst_ab = (const int*)d_in[3];
    const float* val_ab = (const float*)d_in[4];
    const int*   src_ba = (const int*)d_in[5];
    const int*   dst_ba = (const int*)d_in[6];
    const float* val_ba = (const float*)d_in[7];
    const float* W1  = (const float*)d_in[8];
    const float* b1  = (const float*)d_in[9];
    const float* g1  = (const float*)d_in[10];
    const float* be1 = (const float*)d_in[11];
    const float* W2  = (const float*)d_in[12];
    const float* b2  = (const float*)d_in[13];
    const float* g2  = (const float*)d_in[14];
    const float* be2 = (const float*)d_in[15];
    const float* Win  = (const float*)d_in[16];
    const float* bin_ = (const float*)d_in[17];
    const float* Wout = (const float*)d_in[18];
    const float* bout = (const float*)d_in[19];
    const float* lng  = (const float*)d_in[20];
    const float* lnb  = (const float*)d_in[21];
    float* outp = (float*)d_out;

    cudaFuncSetAttribute(k_proj,     cudaFuncAttributeMaxDynamicSharedMemorySize, SMEM_PROJ);
    cudaFuncSetAttribute(k_qkv_attn, cudaFuncAttributeMaxDynamicSharedMemorySize, SMEM_QKV);
    cudaFuncSetAttribute(k_out,      cudaFuncAttributeMaxDynamicSharedMemorySize, SMEM_PROJ);

    // CSR build (dst-grouped), with CSR-sorted src/val
    k_zero_cnt<<<118, 256>>>();
    k_hist<<<1875, 256>>>(dst_ab, dst_ba);
    k_scan<<<2, 1024>>>();
    k_zero_cnt<<<118, 256>>>();
    k_scatter<<<1875, 256>>>(dst_ab, src_ab, val_ab, dst_ba, src_ba, val_ba);

    // spmm + fused l2norm
    k_spmm_ab<<<7500, 256>>>(feat_A);
    k_spmm_ba<<<7500, 256>>>(feat_B);

    // proj -> x (stacked), persistent one-wave grids
    k_proj<<<GRID_GEMM, 256, SMEM_PROJ>>>(W1, b1, g1, be1, 0);
    k_proj<<<GRID_GEMM, 256, SMEM_PROJ>>>(W2, b2, g2, be2, 1);

    // fused qkv + attention -> g_o
    k_qkv_attn<<<GRID_GEMM, 256, SMEM_QKV>>>(Win, bin_);

    // Wout + residual + LN + mean over P
    k_out<<<GRID_GEMM, 256, SMEM_PROJ>>>(Wout, bout, lng, lnb, outp);
}

// round 8
// speedup vs baseline: 1.5878x; 1.1007x over previous
#include <cuda_runtime.h>

// ---------------- problem constants ----------------
#define N_A   30000
#define N_B   30000
#define VV    2
#define DD    128
#define EE    480000
#define PP    2

#define ROWS_H 60000    // N_A*V   (also N_B*V)
#define ROWS_X 120000   // N_A*V*P

// proj_both: W1^T + W2^T (128KB) + prepacked x stage (8 warps * 8 rows * 128 ull = 64KB)
#define SMEM_PROJ2 (2*DD*DD*4 + 8*8*DD*8)        // 196608 -> 1 block/SM
// qkv_attn: Wq^T + Wk^T + Wv^T (192KB) + f32 x stage (8 warps * 6 rows * 128 f32 = 24KB)
#define SMEM_QKV   (3*DD*DD*4 + 8*6*DD*4)        // 221184 -> 1 block/SM
// out: Wout^T (64KB) + prepacked stage (8 warps * 8 rows * 128 ull = 64KB)
#define SMEM_OUT   (DD*DD*4 + 8*8*DD*8)          // 131072 -> 1 block/SM

#define GRID_GEMM 148   // one resident block per SM (persistent)

// ---------------- scratch (device globals; no allocation allowed) ----------------
__device__ int g_cnt_ab[N_B];
__device__ int g_cnt_ba[N_A];
__device__ int g_ptr_ab[N_B + 1];
__device__ int g_ptr_ba[N_A + 1];
__device__ int   g_srcs_ab[EE];   // CSR-sorted src
__device__ float g_vals_ab[EE];   // CSR-sorted val
__device__ int   g_srcs_ba[EE];
__device__ float g_vals_ba[EE];

__device__ float g_hB  [(size_t)N_B * VV * DD];   // l2norm(spmm(feat_A)) at B
__device__ float g_hABA[(size_t)N_A * VV * DD];   // l2norm(spmm(g_hB)) at A
__device__ float g_hBA [(size_t)N_A * VV * DD];   // l2norm(spmm(feat_B)) at A
__device__ float g_x[(size_t)ROWS_X * DD];        // stacked [n][v][p][d]
__device__ float g_o[(size_t)ROWS_X * DD];        // attention output

// ---------------- helpers ----------------
static __device__ __forceinline__ float warp_sum(float v) {
#pragma unroll
    for (int o = 16; o > 0; o >>= 1) v += __shfl_xor_sync(0xffffffffu, v, o);
    return v;
}
static __device__ __forceinline__ float sum8(float v) {
    v += __shfl_xor_sync(0xffffffffu, v, 1);
    v += __shfl_xor_sync(0xffffffffu, v, 2);
    v += __shfl_xor_sync(0xffffffffu, v, 4);
    return v;
}

// packed f32x2 FMA (B300 FFMA2 path: 2x scalar FFMA throughput)
static __device__ __forceinline__ unsigned long long pk2(float x) {
    unsigned long long r;
    asm("mov.b64 %0, {%1, %1};" : "=l"(r) : "f"(x));
    return r;
}
static __device__ __forceinline__ void ffma2(unsigned long long& d,
                                             unsigned long long a,
                                             unsigned long long b) {
    asm("fma.rn.f32x2 %0, %1, %2, %0;" : "+l"(d) : "l"(a), "l"(b));
}
static __device__ __forceinline__ float2 upk2(unsigned long long a) {
    float2 f;
    asm("mov.b64 {%0, %1}, %2;" : "=f"(f.x), "=f"(f.y) : "l"(a));
    return f;
}
static __device__ __forceinline__ float4 acc2f4(const unsigned long long* a) {
    float2 p0 = upk2(a[0]), p1 = upk2(a[1]);
    return make_float4(p0.x, p0.y, p1.x, p1.y);
}

// ---------------- CSR build ----------------
__global__ void k_zero_cnt() {
    int i = blockIdx.x * blockDim.x + threadIdx.x;
    if (i < N_B) g_cnt_ab[i] = 0;
    if (i < N_A) g_cnt_ba[i] = 0;
}

__global__ void k_hist(const int* __restrict__ dst_ab, const int* __restrict__ dst_ba) {
    int e = blockIdx.x * blockDim.x + threadIdx.x;
    if (e < EE) {
        atomicAdd(&g_cnt_ab[dst_ab[e]], 1);
        atomicAdd(&g_cnt_ba[dst_ba[e]], 1);
    }
}

__global__ void k_scan() {
    __shared__ int ssum[1024];
    const int n = N_A;  // both 30000
    int* cnt = (blockIdx.x == 0) ? g_cnt_ab : g_cnt_ba;
    int* ptr = (blockIdx.x == 0) ? g_ptr_ab : g_ptr_ba;
    int t = threadIdx.x;
    const int chunk = (n + 1023) / 1024;
    int b0 = t * chunk;
    int b1 = min(b0 + chunk, n);
    int s = 0;
    for (int i = b0; i < b1; i++) s += cnt[i];
    ssum[t] = s;
    __syncthreads();
#pragma unroll
    for (int off = 1; off < 1024; off <<= 1) {
        int v = (t >= off) ? ssum[t - off] : 0;
        __syncthreads();
        ssum[t] += v;
        __syncthreads();
    }
    int run = (t == 0) ? 0 : ssum[t - 1];
    for (int i = b0; i < b1; i++) { ptr[i] = run; run += cnt[i]; }
    if (t == 1023) ptr[n] = ssum[1023];
}

__global__ void k_scatter(const int* __restrict__ dst_ab, const int* __restrict__ src_ab,
                          const float* __restrict__ val_ab,
                          const int* __restrict__ dst_ba, const int* __restrict__ src_ba,
                          const float* __restrict__ val_ba) {
    int e = blockIdx.x * blockDim.x + threadIdx.x;
    if (e < EE) {
        int d = dst_ab[e];
        int p = g_ptr_ab[d] + atomicAdd(&g_cnt_ab[d], 1);
        g_srcs_ab[p] = src_ab[e];
        g_vals_ab[p] = val_ab[e];
        d = dst_ba[e];
        p = g_ptr_ba[d] + atomicAdd(&g_cnt_ba[d], 1);
        g_srcs_ba[p] = src_ba[e];
        g_vals_ba[p] = val_ba[e];
    }
}

// ---------------- spmm + fused l2norm ----------------
__global__ void k_spmm_ab(const float* __restrict__ feat_A) {
    int w = (blockIdx.x * blockDim.x + threadIdx.x) >> 5;
    int lane = threadIdx.x & 31;
    if (w >= N_B * VV) return;
    int n = w >> 1, v = w & 1;
    int beg = g_ptr_ab[n], end = g_ptr_ab[n + 1];
    float4 acc = make_float4(0.f, 0.f, 0.f, 0.f);
    for (int c = beg; c < end; c += 32) {
        int m = min(32, end - c);
        int s = 0; float vv = 0.f;
        if (lane < m) { s = g_srcs_ab[c + lane]; vv = g_vals_ab[c + lane]; }
        int j = 0;
        for (; j + 4 <= m; j += 4) {
            int s0 = __shfl_sync(0xffffffffu, s, j);
            int s1 = __shfl_sync(0xffffffffu, s, j + 1);
            int s2 = __shfl_sync(0xffffffffu, s, j + 2);
            int s3 = __shfl_sync(0xffffffffu, s, j + 3);
            float u0 = __shfl_sync(0xffffffffu, vv, j);
            float u1 = __shfl_sync(0xffffffffu, vv, j + 1);
            float u2 = __shfl_sync(0xffffffffu, vv, j + 2);
            float u3 = __shfl_sync(0xffffffffu, vv, j + 3);
            const float4 f0 = *reinterpret_cast<const float4*>(feat_A + (((size_t)s0 * VV + v) << 7) + (lane << 2));
            const float4 f1 = *reinterpret_cast<const float4*>(feat_A + (((size_t)s1 * VV + v) << 7) + (lane << 2));
            const float4 f2 = *reinterpret_cast<const float4*>(feat_A + (((size_t)s2 * VV + v) << 7) + (lane << 2));
            const float4 f3 = *reinterpret_cast<const float4*>(feat_A + (((size_t)s3 * VV + v) << 7) + (lane << 2));
            acc.x = fmaf(f0.x, u0, acc.x); acc.y = fmaf(f0.y, u0, acc.y);
            acc.z = fmaf(f0.z, u0, acc.z); acc.w = fmaf(f0.w, u0, acc.w);
            acc.x = fmaf(f1.x, u1, acc.x); acc.y = fmaf(f1.y, u1, acc.y);
            acc.z = fmaf(f1.z, u1, acc.z); acc.w = fmaf(f1.w, u1, acc.w);
            acc.x = fmaf(f2.x, u2, acc.x); acc.y = fmaf(f2.y, u2, acc.y);
            acc.z = fmaf(f2.z, u2, acc.z); acc.w = fmaf(f2.w, u2, acc.w);
            acc.x = fmaf(f3.x, u3, acc.x); acc.y = fmaf(f3.y, u3, acc.y);
            acc.z = fmaf(f3.z, u3, acc.z); acc.w = fmaf(f3.w, u3, acc.w);
        }
        for (; j < m; j++) {
            int sj = __shfl_sync(0xffffffffu, s, j);
            float vj = __shfl_sync(0xffffffffu, vv, j);
            const float4 f = *reinterpret_cast<const float4*>(feat_A + (((size_t)sj * VV + v) << 7) + (lane << 2));
            acc.x = fmaf(f.x, vj, acc.x); acc.y = fmaf(f.y, vj, acc.y);
            acc.z = fmaf(f.z, vj, acc.z); acc.w = fmaf(f.w, vj, acc.w);
        }
    }
    float sq = warp_sum(acc.x * acc.x + acc.y * acc.y + acc.z * acc.z + acc.w * acc.w);
    float inv = 1.f / fmaxf(sqrtf(sq), 1e-12f);
    *reinterpret_cast<float4*>(g_hB + (((size_t)n * VV + v) << 7) + (lane << 2)) =
        make_float4(acc.x * inv, acc.y * inv, acc.z * inv, acc.w * inv);
}

__global__ void k_spmm_ba(const float* __restrict__ feat_B) {
    int w = (blockIdx.x * blockDim.x + threadIdx.x) >> 5;
    int lane = threadIdx.x & 31;
    if (w >= N_A * VV) return;
    int n = w >> 1, v = w & 1;
    int beg = g_ptr_ba[n], end = g_ptr_ba[n + 1];
    float4 a1 = make_float4(0.f, 0.f, 0.f, 0.f);
    float4 a2 = make_float4(0.f, 0.f, 0.f, 0.f);
    for (int c = beg; c < end; c += 32) {
        int m = min(32, end - c);
        int s = 0; float vv = 0.f;
        if (lane < m) { s = g_srcs_ba[c + lane]; vv = g_vals_ba[c + lane]; }
        int j = 0;
        for (; j + 2 <= m; j += 2) {
            int s0 = __shfl_sync(0xffffffffu, s, j);
            int s1 = __shfl_sync(0xffffffffu, s, j + 1);
            float u0 = __shfl_sync(0xffffffffu, vv, j);
            float u1 = __shfl_sync(0xffffffffu, vv, j + 1);
            size_t o0 = (((size_t)s0 * VV + v) << 7) + (lane << 2);
            size_t o1 = (((size_t)s1 * VV + v) << 7) + (lane << 2);
            const float4 p0 = *reinterpret_cast<const float4*>(g_hB + o0);
            const float4 q0 = *reinterpret_cast<const float4*>(feat_B + o0);
            const float4 p1 = *reinterpret_cast<const float4*>(g_hB + o1);
            const float4 q1 = *reinterpret_cast<const float4*>(feat_B + o1);
            a1.x = fmaf(p0.x, u0, a1.x); a1.y = fmaf(p0.y, u0, a1.y);
            a1.z = fmaf(p0.z, u0, a1.z); a1.w = fmaf(p0.w, u0, a1.w);
            a2.x = fmaf(q0.x, u0, a2.x); a2.y = fmaf(q0.y, u0, a2.y);
            a2.z = fmaf(q0.z, u0, a2.z); a2.w = fmaf(q0.w, u0, a2.w);
            a1.x = fmaf(p1.x, u1, a1.x); a1.y = fmaf(p1.y, u1, a1.y);
            a1.z = fmaf(p1.z, u1, a1.z); a1.w = fmaf(p1.w, u1, a1.w);
            a2.x = fmaf(q1.x, u1, a2.x); a2.y = fmaf(q1.y, u1, a2.y);
            a2.z = fmaf(q1.z, u1, a2.z); a2.w = fmaf(q1.w, u1, a2.w);
        }
        for (; j < m; j++) {
            int sj = __shfl_sync(0xffffffffu, s, j);
            float vj = __shfl_sync(0xffffffffu, vv, j);
            size_t off = (((size_t)sj * VV + v) << 7) + (lane << 2);
            const float4 f1 = *reinterpret_cast<const float4*>(g_hB + off);
            const float4 f2 = *reinterpret_cast<const float4*>(feat_B + off);
            a1.x = fmaf(f1.x, vj, a1.x); a1.y = fmaf(f1.y, vj, a1.y);
            a1.z = fmaf(f1.z, vj, a1.z); a1.w = fmaf(f1.w, vj, a1.w);
            a2.x = fmaf(f2.x, vj, a2.x); a2.y = fmaf(f2.y, vj, a2.y);
            a2.z = fmaf(f2.z, vj, a2.z); a2.w = fmaf(f2.w, vj, a2.w);
        }
    }
    size_t outoff = (((size_t)n * VV + v) << 7) + (lane << 2);
    float sq1 = warp_sum(a1.x * a1.x + a1.y * a1.y + a1.z * a1.z + a1.w * a1.w);
    float i1 = 1.f / fmaxf(sqrtf(sq1), 1e-12f);
    *reinterpret_cast<float4*>(g_hABA + outoff) =
        make_float4(a1.x * i1, a1.y * i1, a1.z * i1, a1.w * i1);
    float sq2 = warp_sum(a2.x * a2.x + a2.y * a2.y + a2.z * a2.z + a2.w * a2.w);
    float i2 = 1.f / fmaxf(sqrtf(sq2), 1e-12f);
    *reinterpret_cast<float4*>(g_hBA + outoff) =
        make_float4(a2.x * i2, a2.y * i2, a2.z * i2, a2.w * i2);
}

// ---------------- merged proj (both matrices): relu(LN(in @ W^T + b)) -> g_x ----------------
__global__ void __launch_bounds__(256) k_proj_both(
        const float* __restrict__ W1m, const float* __restrict__ b1m,
        const float* __restrict__ g1m, const float* __restrict__ be1m,
        const float* __restrict__ W2m, const float* __restrict__ b2m,
        const float* __restrict__ g2m, const float* __restrict__ be2m) {
    extern __shared__ float sm[];
    float* sW1 = sm;
    float* sW2 = sm + DD * DD;
    unsigned long long* sX = reinterpret_cast<unsigned long long*>(sm + 2 * DD * DD);
    for (int idx = threadIdx.x; idx < DD * DD; idx += blockDim.x) {
        int j = idx >> 7, k = idx & 127;
        sW1[k * DD + j] = W1m[idx];
        sW2[k * DD + j] = W2m[idx];
    }
    int lane = threadIdx.x & 31, w = threadIdx.x >> 5;
    float4 b4a  = *reinterpret_cast<const float4*>(b1m  + (lane << 2));
    float4 g4a  = *reinterpret_cast<const float4*>(g1m  + (lane << 2));
    float4 be4a = *reinterpret_cast<const float4*>(be1m + (lane << 2));
    float4 b4b  = *reinterpret_cast<const float4*>(b2m  + (lane << 2));
    float4 g4b  = *reinterpret_cast<const float4*>(g2m  + (lane << 2));
    float4 be4b = *reinterpret_cast<const float4*>(be2m + (lane << 2));
    __syncthreads();
    unsigned long long* xr = sX + (size_t)w * 8 * DD;
    const int NTH = ROWS_H / 8;                // 7500 tiles per input
    const int NT = 2 * NTH;                    // 15000 total
    const int TW = GRID_GEMM * 8;
    int gw = blockIdx.x * 8 + w;
    for (int t = gw; t < NT; t += TW) {
        int which = (t >= NTH) ? 1 : 0;
        int base = (which ? (t - NTH) : t) * 8;
        const float* in = which ? g_hBA : g_hABA;
        const float* sWt = which ? sW2 : sW1;
        float4 b4 = which ? b4b : b4a;
        float4 g4 = which ? g4b : g4a;
        float4 be4 = which ? be4b : be4a;
#pragma unroll
        for (int r = 0; r < 8; r++) {
            const float* row = in + (size_t)(base + r) * DD;
#pragma unroll
            for (int c = 0; c < 4; c++)
                xr[r * DD + lane + 32 * c] = pk2(row[lane + 32 * c]);
        }
        __syncwarp();
        unsigned long long acc[8][2];
#pragma unroll
        for (int r = 0; r < 8; r++) { acc[r][0] = 0ull; acc[r][1] = 0ull; }
#pragma unroll 2
        for (int k = 0; k < DD; k += 2) {
            ulonglong2 w0 = *reinterpret_cast<const ulonglong2*>(sWt + k * DD + (lane << 2));
            ulonglong2 w1 = *reinterpret_cast<const ulonglong2*>(sWt + (k + 1) * DD + (lane << 2));
#pragma unroll
            for (int r = 0; r < 8; r++) {
                ulonglong2 xv = *reinterpret_cast<const ulonglong2*>(xr + r * DD + k);
                ffma2(acc[r][0], w0.x, xv.x);
                ffma2(acc[r][1], w0.y, xv.x);
                ffma2(acc[r][0], w1.x, xv.y);
                ffma2(acc[r][1], w1.y, xv.y);
            }
        }
#pragma unroll
        for (int r = 0; r < 8; r++) {
            float4 p = acc2f4(acc[r]);
            float4 tt = make_float4(p.x + b4.x, p.y + b4.y, p.z + b4.z, p.w + b4.w);
            float mu = warp_sum(tt.x + tt.y + tt.z + tt.w) * (1.f / DD);
            float4 d = make_float4(tt.x - mu, tt.y - mu, tt.z - mu, tt.w - mu);
            float var = warp_sum(d.x * d.x + d.y * d.y + d.z * d.z + d.w * d.w) * (1.f / DD);
            float rs = rsqrtf(var + 1e-5f);
            float4 o = make_float4(fmaxf(d.x * rs * g4.x + be4.x, 0.f),
                                   fmaxf(d.y * rs * g4.y + be4.y, 0.f),
                                   fmaxf(d.z * rs * g4.z + be4.z, 0.f),
                                   fmaxf(d.w * rs * g4.w + be4.w, 0.f));
            *reinterpret_cast<float4*>(
                g_x + ((size_t)(base + r) * PP + which) * DD + (lane << 2)) = o;
        }
        __syncwarp();
    }
}

// ---------------- fused qkv + per-head attention -> g_o ----------------
// R=6 rows/warp = 3 (n,v) units; f32 x staging (broadcast loads, pk2 in regs)
__global__ void __launch_bounds__(256) k_qkv_attn(const float* __restrict__ Win,
                                                  const float* __restrict__ bin_) {
    extern __shared__ float sm[];
    float* sWq = sm;                 // [k][j]
    float* sWk = sm + DD * DD;
    float* sWv = sm + 2 * DD * DD;
    float* sX  = sm + 3 * DD * DD;   // f32 stage: 8 warps * 6 rows * 128
    for (int idx = threadIdx.x; idx < DD * DD; idx += blockDim.x) {
        int j = idx >> 7, k = idx & 127;
        sWq[k * DD + j] = Win[idx];
        sWk[k * DD + j] = Win[DD * DD + idx];
        sWv[k * DD + j] = Win[2 * DD * DD + idx];
    }
    int lane = threadIdx.x & 31, w = threadIdx.x >> 5;
    float4 bq = *reinterpret_cast<const float4*>(bin_ + (lane << 2));
    float4 bk = *reinterpret_cast<const float4*>(bin_ + DD + (lane << 2));
    float4 bv = *reinterpret_cast<const float4*>(bin_ + 2 * DD + (lane << 2));
    __syncthreads();
    float* xr = sX + (size_t)w * 6 * DD;
    const float qscale = 0.17677669529663687f;  // 32^-0.5
    const int NWT = ROWS_X / 6;                 // 20000 warp-tiles of 6 rows (3 units)
    const int TW = GRID_GEMM * 8;
    int gw = blockIdx.x * 8 + w;
    for (int t = gw; t < NWT; t += TW) {
        int base = t * 6;
#pragma unroll
        for (int r = 0; r < 6; r++) {
            *reinterpret_cast<float4*>(xr + r * DD + (lane << 2)) =
                *reinterpret_cast<const float4*>(g_x + (size_t)(base + r) * DD + (lane << 2));
        }
        __syncwarp();
        unsigned long long aq[6][2], ak[6][2], av[6][2];
#pragma unroll
        for (int r = 0; r < 6; r++) {
            aq[r][0] = aq[r][1] = 0ull;
            ak[r][0] = ak[r][1] = 0ull;
            av[r][0] = av[r][1] = 0ull;
        }
#pragma unroll 2
        for (int k = 0; k < DD; k += 2) {
            ulonglong2 wq0 = *reinterpret_cast<const ulonglong2*>(sWq + k * DD + (lane << 2));
            ulonglong2 wq1 = *reinterpret_cast<const ulonglong2*>(sWq + (k + 1) * DD + (lane << 2));
            ulonglong2 wk0 = *reinterpret_cast<const ulonglong2*>(sWk + k * DD + (lane << 2));
            ulonglong2 wk1 = *reinterpret_cast<const ulonglong2*>(sWk + (k + 1) * DD + (lane << 2));
            ulonglong2 wv0 = *reinterpret_cast<const ulonglong2*>(sWv + k * DD + (lane << 2));
            ulonglong2 wv1 = *reinterpret_cast<const ulonglong2*>(sWv + (k + 1) * DD + (lane << 2));
#pragma unroll
            for (int r = 0; r < 6; r++) {
                float2 xv = *reinterpret_cast<const float2*>(xr + r * DD + k);  // broadcast
                unsigned long long xa = pk2(xv.x);
                unsigned long long xb = pk2(xv.y);
                ffma2(aq[r][0], wq0.x, xa); ffma2(aq[r][1], wq0.y, xa);
                ffma2(ak[r][0], wk0.x, xa); ffma2(ak[r][1], wk0.y, xa);
                ffma2(av[r][0], wv0.x, xa); ffma2(av[r][1], wv0.y, xa);
                ffma2(aq[r][0], wq1.x, xb); ffma2(aq[r][1], wq1.y, xb);
                ffma2(ak[r][0], wk1.x, xb); ffma2(ak[r][1], wk1.y, xb);
                ffma2(av[r][0], wv1.x, xb); ffma2(av[r][1], wv1.y, xb);
            }
        }
        // per-head attention per (n,v) unit: rows (2u, 2u+1)
#pragma unroll
        for (int u = 0; u < 3; u++) {
            int r0 = 2 * u, r1 = 2 * u + 1;
            float4 q0 = acc2f4(aq[r0]); float4 q1 = acc2f4(aq[r1]);
            float4 k0 = acc2f4(ak[r0]); float4 k1 = acc2f4(ak[r1]);
            float4 v0 = acc2f4(av[r0]); float4 v1 = acc2f4(av[r1]);
            q0.x += bq.x; q0.y += bq.y; q0.z += bq.z; q0.w += bq.w;
            q1.x += bq.x; q1.y += bq.y; q1.z += bq.z; q1.w += bq.w;
            k0.x += bk.x; k0.y += bk.y; k0.z += bk.z; k0.w += bk.w;
            k1.x += bk.x; k1.y += bk.y; k1.z += bk.z; k1.w += bk.w;
            v0.x += bv.x; v0.y += bv.y; v0.z += bv.z; v0.w += bv.w;
            v1.x += bv.x; v1.y += bv.y; v1.z += bv.z; v1.w += bv.w;
            float s00 = sum8(q0.x * k0.x + q0.y * k0.y + q0.z * k0.z + q0.w * k0.w) * qscale;
            float s01 = sum8(q0.x * k1.x + q0.y * k1.y + q0.z * k1.z + q0.w * k1.w) * qscale;
            float s10 = sum8(q1.x * k0.x + q1.y * k0.y + q1.z * k0.z + q1.w * k0.w) * qscale;
            float s11 = sum8(q1.x * k1.x + q1.y * k1.y + q1.z * k1.z + q1.w * k1.w) * qscale;
            float m0 = fmaxf(s00, s01), m1 = fmaxf(s10, s11);
            float e00 = expf(s00 - m0), e01 = expf(s01 - m0);
            float e10 = expf(s10 - m1), e11 = expf(s11 - m1);
            float i0 = 1.f / (e00 + e01), i1 = 1.f / (e10 + e11);
            float a00 = e00 * i0, a01 = e01 * i0;
            float a10 = e10 * i1, a11 = e11 * i1;
            float4 o0 = make_float4(a00 * v0.x + a01 * v1.x, a00 * v0.y + a01 * v1.y,
                                    a00 * v0.z + a01 * v1.z, a00 * v0.w + a01 * v1.w);
            float4 o1 = make_float4(a10 * v0.x + a11 * v1.x, a10 * v0.y + a11 * v1.y,
                                    a10 * v0.z + a11 * v1.z, a10 * v0.w + a11 * v1.w);
            *reinterpret_cast<float4*>(g_o + (size_t)(base + r0) * DD + (lane << 2)) = o0;
            *reinterpret_cast<float4*>(g_o + (size_t)(base + r1) * DD + (lane << 2)) = o1;
        }
        __syncwarp();
    }
}

// ---------------- final: attn = g_o @ Wout^T + bout; LN(attn + g_x); mean over P ----------------
__global__ void __launch_bounds__(256) k_out(
        const float* __restrict__ Wm, const float* __restrict__ bm,
        const float* __restrict__ gm, const float* __restrict__ bem,
        float* __restrict__ outp) {
    extern __shared__ float sm[];
    float* sWt = sm;
    unsigned long long* sX = reinterpret_cast<unsigned long long*>(sm + DD * DD);
    for (int idx = threadIdx.x; idx < DD * DD; idx += blockDim.x) {
        int j = idx >> 7, k = idx & 127;
        sWt[k * DD + j] = Wm[idx];
    }
    int lane = threadIdx.x & 31, w = threadIdx.x >> 5;
    float4 b4  = *reinterpret_cast<const float4*>(bm  + (lane << 2));
    float4 g4  = *reinterpret_cast<const float4*>(gm  + (lane << 2));
    float4 be4 = *reinterpret_cast<const float4*>(bem + (lane << 2));
    __syncthreads();
    unsigned long long* xr = sX + (size_t)w * 8 * DD;
    const int NT = ROWS_X / 8;                 // 15000 tiles of 8 rows
    const int TW = GRID_GEMM * 8;
    int gw = blockIdx.x * 8 + w;
    for (int t = gw; t < NT; t += TW) {
        int base = t * 8;  // 8 rows = 4 (n,v) units
#pragma unroll
        for (int r = 0; r < 8; r++) {
            const float* row = g_o + (size_t)(base + r) * DD;
#pragma unroll
            for (int c = 0; c < 4; c++)
                xr[r * DD + lane + 32 * c] = pk2(row[lane + 32 * c]);
        }
        __syncwarp();
        unsigned long long acc[8][2];
#pragma unroll
        for (int r = 0; r < 8; r++) { acc[r][0] = 0ull; acc[r][1] = 0ull; }
#pragma unroll 2
        for (int k = 0; k < DD; k += 2) {
            ulonglong2 w0 = *reinterpret_cast<const ulonglong2*>(sWt + k * DD + (lane << 2));
            ulonglong2 w1 = *reinterpret_cast<const ulonglong2*>(sWt + (k + 1) * DD + (lane << 2));
#pragma unroll
            for (int r = 0; r < 8; r++) {
                ulonglong2 xv = *reinterpret_cast<const ulonglong2*>(xr + r * DD + k);
                ffma2(acc[r][0], w0.x, xv.x);
                ffma2(acc[r][1], w0.y, xv.x);
                ffma2(acc[r][0], w1.x, xv.y);
                ffma2(acc[r][1], w1.y, xv.y);
            }
        }
        float4 ys[4];
#pragma unroll
        for (int u = 0; u < 4; u++) ys[u] = make_float4(0.f, 0.f, 0.f, 0.f);
#pragma unroll
        for (int r = 0; r < 8; r++) {
            float4 p = acc2f4(acc[r]);
            float4 x4 = *reinterpret_cast<const float4*>(
                g_x + (size_t)(base + r) * DD + (lane << 2));
            float4 tt = make_float4(p.x + b4.x + x4.x, p.y + b4.y + x4.y,
                                    p.z + b4.z + x4.z, p.w + b4.w + x4.w);
            float mu = warp_sum(tt.x + tt.y + tt.z + tt.w) * (1.f / DD);
            float4 d = make_float4(tt.x - mu, tt.y - mu, tt.z - mu, tt.w - mu);
            float var = warp_sum(d.x * d.x + d.y * d.y + d.z * d.z + d.w * d.w) * (1.f / DD);
            float rs = rsqrtf(var + 1e-5f);
            int u = r >> 1;
            ys[u].x += d.x * rs * g4.x + be4.x;
            ys[u].y += d.y * rs * g4.y + be4.y;
            ys[u].z += d.z * rs * g4.z + be4.z;
            ys[u].w += d.w * rs * g4.w + be4.w;
        }
        int u0 = base >> 1;
#pragma unroll
        for (int u = 0; u < 4; u++) {
            *reinterpret_cast<float4*>(outp + (size_t)(u0 + u) * DD + (lane << 2)) =
                make_float4(ys[u].x * 0.5f, ys[u].y * 0.5f, ys[u].z * 0.5f, ys[u].w * 0.5f);
        }
        __syncwarp();
    }
}

// ---------------- launch ----------------
extern "C" void kernel_launch(void* const* d_in, const int* in_sizes, int n_in,
                              void* d_out, int out_size) {
    (void)in_sizes; (void)n_in; (void)out_size;
    const float* feat_A = (const float*)d_in[0];
    const float* feat_B = (const float*)d_in[1];
    const int*   src_ab = (const int*)d_in[2];
    const int*   dst_ab = (const int*)d_in[3];
    const float* val_ab = (const float*)d_in[4];
    const int*   src_ba = (const int*)d_in[5];
    const int*   dst_ba = (const int*)d_in[6];
    const float* val_ba = (const float*)d_in[7];
    const float* W1  = (const float*)d_in[8];
    const float* b1  = (const float*)d_in[9];
    const float* g1  = (const float*)d_in[10];
    const float* be1 = (const float*)d_in[11];
    const float* W2  = (const float*)d_in[12];
    const float* b2  = (const float*)d_in[13];
    const float* g2  = (const float*)d_in[14];
    const float* be2 = (const float*)d_in[15];
    const float* Win  = (const float*)d_in[16];
    const float* bin_ = (const float*)d_in[17];
    const float* Wout = (const float*)d_in[18];
    const float* bout = (const float*)d_in[19];
    const float* lng  = (const float*)d_in[20];
    const float* lnb  = (const float*)d_in[21];
    float* outp = (float*)d_out;

    cudaFuncSetAttribute(k_proj_both, cudaFuncAttributeMaxDynamicSharedMemorySize, SMEM_PROJ2);
    cudaFuncSetAttribute(k_qkv_attn,  cudaFuncAttributeMaxDynamicSharedMemorySize, SMEM_QKV);
    cudaFuncSetAttribute(k_out,       cudaFuncAttributeMaxDynamicSharedMemorySize, SMEM_OUT);

    // CSR build (dst-grouped), with CSR-sorted src/val
    k_zero_cnt<<<118, 256>>>();
    k_hist<<<1875, 256>>>(dst_ab, dst_ba);
    k_scan<<<2, 1024>>>();
    k_zero_cnt<<<118, 256>>>();
    k_scatter<<<1875, 256>>>(dst_ab, src_ab, val_ab, dst_ba, src_ba, val_ba);

    // spmm + fused l2norm
    k_spmm_ab<<<7500, 256>>>(feat_A);
    k_spmm_ba<<<7500, 256>>>(feat_B);

    // both projections -> x (stacked), one persistent launch
    k_proj_both<<<GRID_GEMM, 256, SMEM_PROJ2>>>(W1, b1, g1, be1, W2, b2, g2, be2);

    // fused qkv + per-head attention -> g_o
    k_qkv_attn<<<GRID_GEMM, 256, SMEM_QKV>>>(Win, bin_);

    // Wout + residual + LN + mean over P -> d_out
    k_out<<<GRID_GEMM, 256, SMEM_OUT>>>(Wout, bout, lng, lnb, outp);
}

// round 12
// speedup vs baseline: 1.8754x; 1.1811x over previous
#include <cuda_runtime.h>
#include <cuda_bf16.h>

// ---------------- problem constants ----------------
#define N_A   30000
#define N_B   30000
#define VV    2
#define DD    128
#define EE    480000
#define PP    2

#define ROWS_H 60000    // N_A*V   (also N_B*V)
#define ROWS_X 120000   // N_A*V*P

// qkv_attn (FFMA2): Wq^T+Wk^T+Wv^T (192KB) + f32 x stage (8 warps*6 rows*128 f32 = 24KB)
#define SMEM_QKV   (3*DD*DD*4 + 8*6*DD*4)        // 221184 -> 1 block/SM

// mma kernels: blocked bf16 tiles. W tile = 32768 B (hi or lo). A stage per warp = 8192 B.
#define SMEM_PROJ_MMA (4*32768 + 8*8192 + 6*512)  // 199680
#define PROJ_AOFF     (4*32768)                   // 131072
#define PROJ_BOFF2    (4*32768 + 8*8192)          // 196608
#define SMEM_OUT_MMA  (2*32768 + 8*8192 + 3*512)  // 132608
#define OUT_AOFF      (2*32768)                   // 65536
#define OUT_BOFF2     (2*32768 + 8*8192)          // 131072

#define GRID_GEMM 148

typedef unsigned long long u64;

// ---------------- scratch (device globals; no allocation allowed) ----------------
__device__ int g_cnt_ab[N_B];
__device__ int g_cnt_ba[N_A];
__device__ int g_ptr_ab[N_B + 1];
__device__ int g_ptr_ba[N_A + 1];
__device__ int   g_srcs_ab[EE];
__device__ float g_vals_ab[EE];
__device__ int   g_srcs_ba[EE];
__device__ float g_vals_ba[EE];

__device__ float g_hB  [(size_t)N_B * VV * DD];
__device__ float g_hABA[(size_t)N_A * VV * DD];
__device__ float g_hBA [(size_t)N_A * VV * DD];
__device__ float g_x[(size_t)ROWS_X * DD];
__device__ float g_o[(size_t)ROWS_X * DD];

// ---------------- generic helpers ----------------
static __device__ __forceinline__ float warp_sum(float v) {
#pragma unroll
    for (int o = 16; o > 0; o >>= 1) v += __shfl_xor_sync(0xffffffffu, v, o);
    return v;
}
static __device__ __forceinline__ float sum8(float v) {
    v += __shfl_xor_sync(0xffffffffu, v, 1);
    v += __shfl_xor_sync(0xffffffffu, v, 2);
    v += __shfl_xor_sync(0xffffffffu, v, 4);
    return v;
}
static __device__ __forceinline__ u64 pk2(float x) {
    u64 r;
    asm("mov.b64 %0, {%1, %1};" : "=l"(r) : "f"(x));
    return r;
}
static __device__ __forceinline__ void ffma2(u64& d, u64 a, u64 b) {
    asm("fma.rn.f32x2 %0, %1, %2, %0;" : "+l"(d) : "l"(a), "l"(b));
}
static __device__ __forceinline__ float2 upk2(u64 a) {
    float2 f;
    asm("mov.b64 {%0, %1}, %2;" : "=f"(f.x), "=f"(f.y) : "l"(a));
    return f;
}
static __device__ __forceinline__ float4 acc2f4(const u64* a) {
    float2 p0 = upk2(a[0]), p1 = upk2(a[1]);
    return make_float4(p0.x, p0.y, p1.x, p1.y);
}
static __device__ __forceinline__ unsigned smem_u32(const void* p) {
    unsigned a;
    asm("{ .reg .u64 t; cvta.to.shared.u64 t, %1; cvt.u32.u64 %0, t; }" : "=r"(a) : "l"(p));
    return a;
}

// ---------------- mma.sync helpers (sm_80-baseline ISA; NO tcgen05) ----------------
static __device__ __forceinline__ void ldsm4(unsigned* r, unsigned addr) {
    asm volatile("ldmatrix.sync.aligned.m8n8.x4.shared.b16 {%0,%1,%2,%3}, [%4];"
                 : "=r"(r[0]), "=r"(r[1]), "=r"(r[2]), "=r"(r[3]) : "r"(addr));
}
static __device__ __forceinline__ void ldsm2(unsigned& r0, unsigned& r1, unsigned addr) {
    asm volatile("ldmatrix.sync.aligned.m8n8.x2.shared.b16 {%0,%1}, [%2];"
                 : "=r"(r0), "=r"(r1) : "r"(addr));
}
static __device__ __forceinline__ void mma16816(float* d, const unsigned* a,
                                                unsigned b0, unsigned b1) {
    asm volatile("mma.sync.aligned.m16n8k16.row.col.f32.bf16.bf16.f32 "
                 "{%0,%1,%2,%3}, {%4,%5,%6,%7}, {%8,%9}, {%0,%1,%2,%3};"
                 : "+f"(d[0]), "+f"(d[1]), "+f"(d[2]), "+f"(d[3])
                 : "r"(a[0]), "r"(a[1]), "r"(a[2]), "r"(a[3]), "r"(b0), "r"(b1));
}

static __device__ __forceinline__ unsigned short bf_bits(__nv_bfloat16 h) {
    return *reinterpret_cast<unsigned short*>(&h);
}
// float4 -> packed bf16 hi (u64) + lo (u64)
static __device__ __forceinline__ void split4(float4 f, u64& hi, u64& lo) {
    __nv_bfloat16 h0 = __float2bfloat16(f.x), h1 = __float2bfloat16(f.y);
    __nv_bfloat16 h2 = __float2bfloat16(f.z), h3 = __float2bfloat16(f.w);
    __nv_bfloat16 l0 = __float2bfloat16(f.x - __bfloat162float(h0));
    __nv_bfloat16 l1 = __float2bfloat16(f.y - __bfloat162float(h1));
    __nv_bfloat16 l2 = __float2bfloat16(f.z - __bfloat162float(h2));
    __nv_bfloat16 l3 = __float2bfloat16(f.w - __bfloat162float(h3));
    hi = (u64)bf_bits(h0) | ((u64)bf_bits(h1) << 16)
       | ((u64)bf_bits(h2) << 32) | ((u64)bf_bits(h3) << 48);
    lo = (u64)bf_bits(l0) | ((u64)bf_bits(l1) << 16)
       | ((u64)bf_bits(l2) << 32) | ((u64)bf_bits(l3) << 48);
}

// Stage W (128x128 f32) into blocked bf16 hi/lo B-tiles.
// B block (nb,kb) = 8 n-rows x 16 k: at (nb*8+kb)*256; sub8x8 s = kc>>3 at s*128;
// elem (n, kc): + (n&7)*16 + (kc&7)*2. ldmatrix.x2 addr = blockbase + (lane&15)*16.
static __device__ __forceinline__ void stage_W(char* smc, int off_hi, int off_lo,
                                               const float* W, int tid) {
    for (int idx = tid; idx < 4096; idx += 256) {
        int j = idx >> 5;               // n 0..127
        int kq = (idx & 31) << 2;       // k quad
        float4 f = *reinterpret_cast<const float4*>(W + j * DD + kq);
        u64 hi, lo; split4(f, hi, lo);
        unsigned off = (unsigned)((((j >> 3) * 8 + (kq >> 4)) * 256) +
                                  (((kq >> 3) & 1) * 128) + ((j & 7) * 16) + ((kq & 7) * 2));
        *reinterpret_cast<u64*>(smc + off_hi + off) = hi;
        *reinterpret_cast<u64*>(smc + off_lo + off) = lo;
    }
}

// Stage 16x128 f32 rows into blocked bf16 hi/lo A-tiles (per warp).
// A block kb = 16 rows x 16 k at kb*512; sub8x8 s = (r>>3)|((kc>>3)<<1) at s*128;
// elem: + (r&7)*16 + (kc&7)*2. ldmatrix.x4 addr = base + kb*512 + lane*16.
static __device__ __forceinline__ void stage_A16(char* smc, int off_hi, int off_lo,
                                                 const float* src, int lane) {
#pragma unroll
    for (int i = 0; i < 16; i++) {
        int idx = lane + i * 32;
        int r = idx >> 5;
        int kq = (idx & 31) << 2;
        float4 f = *reinterpret_cast<const float4*>(src + (size_t)r * DD + kq);
        u64 hi, lo; split4(f, hi, lo);
        unsigned off = (unsigned)(((kq >> 4) * 512) +
                                  ((((r >> 3) | (((kq >> 3) & 1) << 1))) * 128) +
                                  ((r & 7) * 16) + ((kq & 7) * 2));
        *reinterpret_cast<u64*>(smc + off_hi + off) = hi;
        *reinterpret_cast<u64*>(smc + off_lo + off) = lo;
    }
}

// 3-pass bf16-split GEMM core for one 16x128 tile: acc[16][4] += X(16x128) @ W^T(128x128)
static __device__ __forceinline__ void mma_core(float acc[16][4],
                                                unsigned aBaseH, unsigned aBaseL,
                                                unsigned wH, unsigned wL, int lane) {
    unsigned ah[8][4], al[8][4];
#pragma unroll
    for (int kb = 0; kb < 8; kb++) {
        ldsm4(ah[kb], aBaseH + kb * 512 + lane * 16);
        ldsm4(al[kb], aBaseL + kb * 512 + lane * 16);
    }
#pragma unroll
    for (int kb = 0; kb < 8; kb++) {
#pragma unroll
        for (int nb = 0; nb < 16; nb++) {
            unsigned boff = (unsigned)((nb * 8 + kb) * 256 + (lane & 15) * 16);
            unsigned bh0, bh1, bl0, bl1;
            ldsm2(bh0, bh1, wH + boff);
            ldsm2(bl0, bl1, wL + boff);
            mma16816(acc[nb], ah[kb], bh0, bh1);
            mma16816(acc[nb], ah[kb], bl0, bl1);
            mma16816(acc[nb], al[kb], bh0, bh1);
        }
    }
}

// ---------------- CSR build ----------------
__global__ void k_zero_cnt() {
    int i = blockIdx.x * blockDim.x + threadIdx.x;
    if (i < N_B) g_cnt_ab[i] = 0;
    if (i < N_A) g_cnt_ba[i] = 0;
}

__global__ void k_hist(const int* __restrict__ dst_ab, const int* __restrict__ dst_ba) {
    int e = blockIdx.x * blockDim.x + threadIdx.x;
    if (e < EE) {
        atomicAdd(&g_cnt_ab[dst_ab[e]], 1);
        atomicAdd(&g_cnt_ba[dst_ba[e]], 1);
    }
}

__global__ void k_scan() {
    __shared__ int ssum[1024];
    const int n = N_A;
    int* cnt = (blockIdx.x == 0) ? g_cnt_ab : g_cnt_ba;
    int* ptr = (blockIdx.x == 0) ? g_ptr_ab : g_ptr_ba;
    int t = threadIdx.x;
    const int chunk = (n + 1023) / 1024;
    int b0 = t * chunk;
    int b1 = min(b0 + chunk, n);
    int s = 0;
    for (int i = b0; i < b1; i++) s += cnt[i];
    ssum[t] = s;
    __syncthreads();
#pragma unroll
    for (int off = 1; off < 1024; off <<= 1) {
        int v = (t >= off) ? ssum[t - off] : 0;
        __syncthreads();
        ssum[t] += v;
        __syncthreads();
    }
    int run = (t == 0) ? 0 : ssum[t - 1];
    for (int i = b0; i < b1; i++) { ptr[i] = run; run += cnt[i]; }
    if (t == 1023) ptr[n] = ssum[1023];
}

__global__ void k_scatter(const int* __restrict__ dst_ab, const int* __restrict__ src_ab,
                          const float* __restrict__ val_ab,
                          const int* __restrict__ dst_ba, const int* __restrict__ src_ba,
                          const float* __restrict__ val_ba) {
    int e = blockIdx.x * blockDim.x + threadIdx.x;
    if (e < EE) {
        int d = dst_ab[e];
        int p = g_ptr_ab[d] + atomicAdd(&g_cnt_ab[d], 1);
        g_srcs_ab[p] = src_ab[e];
        g_vals_ab[p] = val_ab[e];
        d = dst_ba[e];
        p = g_ptr_ba[d] + atomicAdd(&g_cnt_ba[d], 1);
        g_srcs_ba[p] = src_ba[e];
        g_vals_ba[p] = val_ba[e];
    }
}

// ---------------- spmm + fused l2norm ----------------
__global__ void k_spmm_ab(const float* __restrict__ feat_A) {
    int w = (blockIdx.x * blockDim.x + threadIdx.x) >> 5;
    int lane = threadIdx.x & 31;
    if (w >= N_B * VV) return;
    int n = w >> 1, v = w & 1;
    int beg = g_ptr_ab[n], end = g_ptr_ab[n + 1];
    float4 acc = make_float4(0.f, 0.f, 0.f, 0.f);
    for (int c = beg; c < end; c += 32) {
        int m = min(32, end - c);
        int s = 0; float vv = 0.f;
        if (lane < m) { s = g_srcs_ab[c + lane]; vv = g_vals_ab[c + lane]; }
        int j = 0;
        for (; j + 4 <= m; j += 4) {
            int s0 = __shfl_sync(0xffffffffu, s, j);
            int s1 = __shfl_sync(0xffffffffu, s, j + 1);
            int s2 = __shfl_sync(0xffffffffu, s, j + 2);
            int s3 = __shfl_sync(0xffffffffu, s, j + 3);
            float u0 = __shfl_sync(0xffffffffu, vv, j);
            float u1 = __shfl_sync(0xffffffffu, vv, j + 1);
            float u2 = __shfl_sync(0xffffffffu, vv, j + 2);
            float u3 = __shfl_sync(0xffffffffu, vv, j + 3);
            const float4 f0 = *reinterpret_cast<const float4*>(feat_A + (((size_t)s0 * VV + v) << 7) + (lane << 2));
            const float4 f1 = *reinterpret_cast<const float4*>(feat_A + (((size_t)s1 * VV + v) << 7) + (lane << 2));
            const float4 f2 = *reinterpret_cast<const float4*>(feat_A + (((size_t)s2 * VV + v) << 7) + (lane << 2));
            const float4 f3 = *reinterpret_cast<const float4*>(feat_A + (((size_t)s3 * VV + v) << 7) + (lane << 2));
            acc.x = fmaf(f0.x, u0, acc.x); acc.y = fmaf(f0.y, u0, acc.y);
            acc.z = fmaf(f0.z, u0, acc.z); acc.w = fmaf(f0.w, u0, acc.w);
            acc.x = fmaf(f1.x, u1, acc.x); acc.y = fmaf(f1.y, u1, acc.y);
            acc.z = fmaf(f1.z, u1, acc.z); acc.w = fmaf(f1.w, u1, acc.w);
            acc.x = fmaf(f2.x, u2, acc.x); acc.y = fmaf(f2.y, u2, acc.y);
            acc.z = fmaf(f2.z, u2, acc.z); acc.w = fmaf(f2.w, u2, acc.w);
            acc.x = fmaf(f3.x, u3, acc.x); acc.y = fmaf(f3.y, u3, acc.y);
            acc.z = fmaf(f3.z, u3, acc.z); acc.w = fmaf(f3.w, u3, acc.w);
        }
        for (; j < m; j++) {
            int sj = __shfl_sync(0xffffffffu, s, j);
            float vj = __shfl_sync(0xffffffffu, vv, j);
            const float4 f = *reinterpret_cast<const float4*>(feat_A + (((size_t)sj * VV + v) << 7) + (lane << 2));
            acc.x = fmaf(f.x, vj, acc.x); acc.y = fmaf(f.y, vj, acc.y);
            acc.z = fmaf(f.z, vj, acc.z); acc.w = fmaf(f.w, vj, acc.w);
        }
    }
    float sq = warp_sum(acc.x * acc.x + acc.y * acc.y + acc.z * acc.z + acc.w * acc.w);
    float inv = 1.f / fmaxf(sqrtf(sq), 1e-12f);
    *reinterpret_cast<float4*>(g_hB + (((size_t)n * VV + v) << 7) + (lane << 2)) =
        make_float4(acc.x * inv, acc.y * inv, acc.z * inv, acc.w * inv);
}

__global__ void k_spmm_ba(const float* __restrict__ feat_B) {
    int w = (blockIdx.x * blockDim.x + threadIdx.x) >> 5;
    int lane = threadIdx.x & 31;
    if (w >= N_A * VV) return;
    int n = w >> 1, v = w & 1;
    int beg = g_ptr_ba[n], end = g_ptr_ba[n + 1];
    float4 a1 = make_float4(0.f, 0.f, 0.f, 0.f);
    float4 a2 = make_float4(0.f, 0.f, 0.f, 0.f);
    for (int c = beg; c < end; c += 32) {
        int m = min(32, end - c);
        int s = 0; float vv = 0.f;
        if (lane < m) { s = g_srcs_ba[c + lane]; vv = g_vals_ba[c + lane]; }
        int j = 0;
        for (; j + 2 <= m; j += 2) {
            int s0 = __shfl_sync(0xffffffffu, s, j);
            int s1 = __shfl_sync(0xffffffffu, s, j + 1);
            float u0 = __shfl_sync(0xffffffffu, vv, j);
            float u1 = __shfl_sync(0xffffffffu, vv, j + 1);
            size_t o0 = (((size_t)s0 * VV + v) << 7) + (lane << 2);
            size_t o1 = (((size_t)s1 * VV + v) << 7) + (lane << 2);
            const float4 p0 = *reinterpret_cast<const float4*>(g_hB + o0);
            const float4 q0 = *reinterpret_cast<const float4*>(feat_B + o0);
            const float4 p1 = *reinterpret_cast<const float4*>(g_hB + o1);
            const float4 q1 = *reinterpret_cast<const float4*>(feat_B + o1);
            a1.x = fmaf(p0.x, u0, a1.x); a1.y = fmaf(p0.y, u0, a1.y);
            a1.z = fmaf(p0.z, u0, a1.z); a1.w = fmaf(p0.w, u0, a1.w);
            a2.x = fmaf(q0.x, u0, a2.x); a2.y = fmaf(q0.y, u0, a2.y);
            a2.z = fmaf(q0.z, u0, a2.z); a2.w = fmaf(q0.w, u0, a2.w);
            a1.x = fmaf(p1.x, u1, a1.x); a1.y = fmaf(p1.y, u1, a1.y);
            a1.z = fmaf(p1.z, u1, a1.z); a1.w = fmaf(p1.w, u1, a1.w);
            a2.x = fmaf(q1.x, u1, a2.x); a2.y = fmaf(q1.y, u1, a2.y);
            a2.z = fmaf(q1.z, u1, a2.z); a2.w = fmaf(q1.w, u1, a2.w);
        }
        for (; j < m; j++) {
            int sj = __shfl_sync(0xffffffffu, s, j);
            float vj = __shfl_sync(0xffffffffu, vv, j);
            size_t off = (((size_t)sj * VV + v) << 7) + (lane << 2);
            const float4 f1 = *reinterpret_cast<const float4*>(g_hB + off);
            const float4 f2 = *reinterpret_cast<const float4*>(feat_B + off);
            a1.x = fmaf(f1.x, vj, a1.x); a1.y = fmaf(f1.y, vj, a1.y);
            a1.z = fmaf(f1.z, vj, a1.z); a1.w = fmaf(f1.w, vj, a1.w);
            a2.x = fmaf(f2.x, vj, a2.x); a2.y = fmaf(f2.y, vj, a2.y);
            a2.z = fmaf(f2.z, vj, a2.z); a2.w = fmaf(f2.w, vj, a2.w);
        }
    }
    size_t outoff = (((size_t)n * VV + v) << 7) + (lane << 2);
    float sq1 = warp_sum(a1.x * a1.x + a1.y * a1.y + a1.z * a1.z + a1.w * a1.w);
    float i1 = 1.f / fmaxf(sqrtf(sq1), 1e-12f);
    *reinterpret_cast<float4*>(g_hABA + outoff) =
        make_float4(a1.x * i1, a1.y * i1, a1.z * i1, a1.w * i1);
    float sq2 = warp_sum(a2.x * a2.x + a2.y * a2.y + a2.z * a2.z + a2.w * a2.w);
    float i2 = 1.f / fmaxf(sqrtf(sq2), 1e-12f);
    *reinterpret_cast<float4*>(g_hBA + outoff) =
        make_float4(a2.x * i2, a2.y * i2, a2.z * i2, a2.w * i2);
}

// ---------------- mma.sync proj (both matrices): relu(LN(in @ W^T + b)) -> g_x ----------------
__global__ void __launch_bounds__(256) k_proj_mma(
        const float* __restrict__ W1m, const float* __restrict__ b1m,
        const float* __restrict__ g1m, const float* __restrict__ be1m,
        const float* __restrict__ W2m, const float* __restrict__ b2m,
        const float* __restrict__ g2m, const float* __restrict__ be2m) {
    extern __shared__ char smc[];
    unsigned sbase = smem_u32(smc);
    int tid = threadIdx.x, wid = tid >> 5, lane = tid & 31;

    stage_W(smc, 0,     32768, W1m, tid);
    stage_W(smc, 65536, 98304, W2m, tid);
    float* sB = reinterpret_cast<float*>(smc + PROJ_BOFF2);
    if (tid < 128) {
        sB[tid]       = b1m[tid];  sB[128 + tid] = g1m[tid];  sB[256 + tid] = be1m[tid];
        sB[384 + tid] = b2m[tid];  sB[512 + tid] = g2m[tid];  sB[640 + tid] = be2m[tid];
    }
    __syncthreads();

    int aoff = PROJ_AOFF + wid * 8192;
    unsigned aBaseH = sbase + aoff, aBaseL = aBaseH + 4096;
    const int NTH = ROWS_H / 16;   // 3750 (exact)
    const int c0 = 2 * (lane & 3);
    const int r0 = lane >> 2;
    for (int t = blockIdx.x * 8 + wid; t < 2 * NTH; t += GRID_GEMM * 8) {
        int which = (t >= NTH) ? 1 : 0;
        int base = (which ? (t - NTH) : t) * 16;
        const float* src = (which ? g_hBA : g_hABA) + (size_t)base * DD;
        stage_A16(smc, aoff, aoff + 4096, src, lane);
        __syncwarp();

        float acc[16][4];
#pragma unroll
        for (int nb = 0; nb < 16; nb++) {
            acc[nb][0] = acc[nb][1] = acc[nb][2] = acc[nb][3] = 0.f;
        }
        unsigned wH = sbase + which * 65536, wL = wH + 32768;
        mma_core(acc, aBaseH, aBaseL, wH, wL, lane);

        const float* bb = sB + which * 384;
        const float* gg = bb + 128;
        const float* ee = bb + 256;
        float s0 = 0.f, q0 = 0.f, s1 = 0.f, q1 = 0.f;
#pragma unroll
        for (int nb = 0; nb < 16; nb++) {
            int c = nb * 8 + c0;
            float bv0 = bb[c], bv1 = bb[c + 1];
            acc[nb][0] += bv0; acc[nb][1] += bv1;
            acc[nb][2] += bv0; acc[nb][3] += bv1;
            s0 += acc[nb][0] + acc[nb][1];
            q0 += acc[nb][0] * acc[nb][0] + acc[nb][1] * acc[nb][1];
            s1 += acc[nb][2] + acc[nb][3];
            q1 += acc[nb][2] * acc[nb][2] + acc[nb][3] * acc[nb][3];
        }
        s0 += __shfl_xor_sync(0xffffffffu, s0, 1); s0 += __shfl_xor_sync(0xffffffffu, s0, 2);
        q0 += __shfl_xor_sync(0xffffffffu, q0, 1); q0 += __shfl_xor_sync(0xffffffffu, q0, 2);
        s1 += __shfl_xor_sync(0xffffffffu, s1, 1); s1 += __shfl_xor_sync(0xffffffffu, s1, 2);
        q1 += __shfl_xor_sync(0xffffffffu, q1, 1); q1 += __shfl_xor_sync(0xffffffffu, q1, 2);
        float mu0 = s0 * (1.f / DD), rs0 = rsqrtf(q0 * (1.f / DD) - mu0 * mu0 + 1e-5f);
        float mu1 = s1 * (1.f / DD), rs1 = rsqrtf(q1 * (1.f / DD) - mu1 * mu1 + 1e-5f);

        float* o0 = g_x + ((size_t)(base + r0) * PP + which) * DD;
        float* o1 = g_x + ((size_t)(base + r0 + 8) * PP + which) * DD;
#pragma unroll
        for (int nb = 0; nb < 16; nb++) {
            int c = nb * 8 + c0;
            float g0v = gg[c], g1v = gg[c + 1], e0v = ee[c], e1v = ee[c + 1];
            *reinterpret_cast<float2*>(o0 + c) = make_float2(
                fmaxf((acc[nb][0] - mu0) * rs0 * g0v + e0v, 0.f),
                fmaxf((acc[nb][1] - mu0) * rs0 * g1v + e1v, 0.f));
            *reinterpret_cast<float2*>(o1 + c) = make_float2(
                fmaxf((acc[nb][2] - mu1) * rs1 * g0v + e0v, 0.f),
                fmaxf((acc[nb][3] - mu1) * rs1 * g1v + e1v, 0.f));
        }
        __syncwarp();
    }
}

// ---------------- fused qkv + per-head attention -> g_o (FFMA2, unchanged from R8) ----------------
__global__ void __launch_bounds__(256) k_qkv_attn(const float* __restrict__ Win,
                                                  const float* __restrict__ bin_) {
    extern __shared__ float sm[];
    float* sWq = sm;
    float* sWk = sm + DD * DD;
    float* sWv = sm + 2 * DD * DD;
    float* sX  = sm + 3 * DD * DD;
    for (int idx = threadIdx.x; idx < DD * DD; idx += blockDim.x) {
        int j = idx >> 7, k = idx & 127;
        sWq[k * DD + j] = Win[idx];
        sWk[k * DD + j] = Win[DD * DD + idx];
        sWv[k * DD + j] = Win[2 * DD * DD + idx];
    }
    int lane = threadIdx.x & 31, w = threadIdx.x >> 5;
    float4 bq = *reinterpret_cast<const float4*>(bin_ + (lane << 2));
    float4 bk = *reinterpret_cast<const float4*>(bin_ + DD + (lane << 2));
    float4 bv = *reinterpret_cast<const float4*>(bin_ + 2 * DD + (lane << 2));
    __syncthreads();
    float* xr = sX + (size_t)w * 6 * DD;
    const float qscale = 0.17677669529663687f;
    const int NWT = ROWS_X / 6;
    const int TW = GRID_GEMM * 8;
    int gw = blockIdx.x * 8 + w;
    for (int t = gw; t < NWT; t += TW) {
        int base = t * 6;
#pragma unroll
        for (int r = 0; r < 6; r++) {
            *reinterpret_cast<float4*>(xr + r * DD + (lane << 2)) =
                *reinterpret_cast<const float4*>(g_x + (size_t)(base + r) * DD + (lane << 2));
        }
        __syncwarp();
        u64 aq[6][2], ak[6][2], av[6][2];
#pragma unroll
        for (int r = 0; r < 6; r++) {
            aq[r][0] = aq[r][1] = 0ull;
            ak[r][0] = ak[r][1] = 0ull;
            av[r][0] = av[r][1] = 0ull;
        }
#pragma unroll 2
        for (int k = 0; k < DD; k += 2) {
            ulonglong2 wq0 = *reinterpret_cast<const ulonglong2*>(sWq + k * DD + (lane << 2));
            ulonglong2 wq1 = *reinterpret_cast<const ulonglong2*>(sWq + (k + 1) * DD + (lane << 2));
            ulonglong2 wk0 = *reinterpret_cast<const ulonglong2*>(sWk + k * DD + (lane << 2));
            ulonglong2 wk1 = *reinterpret_cast<const ulonglong2*>(sWk + (k + 1) * DD + (lane << 2));
            ulonglong2 wv0 = *reinterpret_cast<const ulonglong2*>(sWv + k * DD + (lane << 2));
            ulonglong2 wv1 = *reinterpret_cast<const ulonglong2*>(sWv + (k + 1) * DD + (lane << 2));
#pragma unroll
            for (int r = 0; r < 6; r++) {
                float2 xv = *reinterpret_cast<const float2*>(xr + r * DD + k);
                u64 xa = pk2(xv.x);
                u64 xb = pk2(xv.y);
                ffma2(aq[r][0], wq0.x, xa); ffma2(aq[r][1], wq0.y, xa);
                ffma2(ak[r][0], wk0.x, xa); ffma2(ak[r][1], wk0.y, xa);
                ffma2(av[r][0], wv0.x, xa); ffma2(av[r][1], wv0.y, xa);
                ffma2(aq[r][0], wq1.x, xb); ffma2(aq[r][1], wq1.y, xb);
                ffma2(ak[r][0], wk1.x, xb); ffma2(ak[r][1], wk1.y, xb);
                ffma2(av[r][0], wv1.x, xb); ffma2(av[r][1], wv1.y, xb);
            }
        }
#pragma unroll
        for (int u = 0; u < 3; u++) {
            int r0 = 2 * u, r1 = 2 * u + 1;
            float4 q0 = acc2f4(aq[r0]); float4 q1 = acc2f4(aq[r1]);
            float4 k0 = acc2f4(ak[r0]); float4 k1 = acc2f4(ak[r1]);
            float4 v0 = acc2f4(av[r0]); float4 v1 = acc2f4(av[r1]);
            q0.x += bq.x; q0.y += bq.y; q0.z += bq.z; q0.w += bq.w;
            q1.x += bq.x; q1.y += bq.y; q1.z += bq.z; q1.w += bq.w;
            k0.x += bk.x; k0.y += bk.y; k0.z += bk.z; k0.w += bk.w;
            k1.x += bk.x; k1.y += bk.y; k1.z += bk.z; k1.w += bk.w;
            v0.x += bv.x; v0.y += bv.y; v0.z += bv.z; v0.w += bv.w;
            v1.x += bv.x; v1.y += bv.y; v1.z += bv.z; v1.w += bv.w;
            float s00 = sum8(q0.x * k0.x + q0.y * k0.y + q0.z * k0.z + q0.w * k0.w) * qscale;
            float s01 = sum8(q0.x * k1.x + q0.y * k1.y + q0.z * k1.z + q0.w * k1.w) * qscale;
            float s10 = sum8(q1.x * k0.x + q1.y * k0.y + q1.z * k0.z + q1.w * k0.w) * qscale;
            float s11 = sum8(q1.x * k1.x + q1.y * k1.y + q1.z * k1.z + q1.w * k1.w) * qscale;
            float m0 = fmaxf(s00, s01), m1 = fmaxf(s10, s11);
            float e00 = expf(s00 - m0), e01 = expf(s01 - m0);
            float e10 = expf(s10 - m1), e11 = expf(s11 - m1);
            float i0 = 1.f / (e00 + e01), i1 = 1.f / (e10 + e11);
            float a00 = e00 * i0, a01 = e01 * i0;
            float a10 = e10 * i1, a11 = e11 * i1;
            float4 o0 = make_float4(a00 * v0.x + a01 * v1.x, a00 * v0.y + a01 * v1.y,
                                    a00 * v0.z + a01 * v1.z, a00 * v0.w + a01 * v1.w);
            float4 o1 = make_float4(a10 * v0.x + a11 * v1.x, a10 * v0.y + a11 * v1.y,
                                    a10 * v0.z + a11 * v1.z, a10 * v0.w + a11 * v1.w);
            *reinterpret_cast<float4*>(g_o + (size_t)(base + r0) * DD + (lane << 2)) = o0;
            *reinterpret_cast<float4*>(g_o + (size_t)(base + r1) * DD + (lane << 2)) = o1;
        }
        __syncwarp();
    }
}

// ---------------- mma.sync out: g_o @ Wout^T + bout; LN(+g_x); mean over P -> d_out ----------------
__global__ void __launch_bounds__(256) k_out_mma(
        const float* __restrict__ Wm, const float* __restrict__ bm,
        const float* __restrict__ gm, const float* __restrict__ bem,
        float* __restrict__ outp) {
    extern __shared__ char smc[];
    unsigned sbase = smem_u32(smc);
    int tid = threadIdx.x, wid = tid >> 5, lane = tid & 31;

    stage_W(smc, 0, 32768, Wm, tid);
    float* sB = reinterpret_cast<float*>(smc + OUT_BOFF2);
    if (tid < 128) {
        sB[tid] = bm[tid];  sB[128 + tid] = gm[tid];  sB[256 + tid] = bem[tid];
    }
    __syncthreads();

    int aoff = OUT_AOFF + wid * 8192;
    unsigned aBaseH = sbase + aoff, aBaseL = aBaseH + 4096;
    unsigned wH = sbase, wL = sbase + 32768;
    const int NT = ROWS_X / 16;   // 7500 (exact)
    const int c0 = 2 * (lane & 3);
    const int r0 = lane >> 2;
    const bool store = (lane & 4) == 0;   // even-numbered row within pair
    for (int t = blockIdx.x * 8 + wid; t < NT; t += GRID_GEMM * 8) {
        int base = t * 16;
        stage_A16(smc, aoff, aoff + 4096, g_o + (size_t)base * DD, lane);
        __syncwarp();

        float acc[16][4];
#pragma unroll
        for (int nb = 0; nb < 16; nb++) {
            acc[nb][0] = acc[nb][1] = acc[nb][2] = acc[nb][3] = 0.f;
        }
        mma_core(acc, aBaseH, aBaseL, wH, wL, lane);

        // bias + residual, then per-row LN stats
        const float* xr0 = g_x + (size_t)(base + r0) * DD;
        const float* xr1 = g_x + (size_t)(base + r0 + 8) * DD;
        float s0 = 0.f, q0 = 0.f, s1 = 0.f, q1 = 0.f;
#pragma unroll
        for (int nb = 0; nb < 16; nb++) {
            int c = nb * 8 + c0;
            float2 x0 = *reinterpret_cast<const float2*>(xr0 + c);
            float2 x1 = *reinterpret_cast<const float2*>(xr1 + c);
            float bv0 = sB[c], bv1 = sB[c + 1];
            acc[nb][0] += bv0 + x0.x;  acc[nb][1] += bv1 + x0.y;
            acc[nb][2] += bv0 + x1.x;  acc[nb][3] += bv1 + x1.y;
            s0 += acc[nb][0] + acc[nb][1];
            q0 += acc[nb][0] * acc[nb][0] + acc[nb][1] * acc[nb][1];
            s1 += acc[nb][2] + acc[nb][3];
            q1 += acc[nb][2] * acc[nb][2] + acc[nb][3] * acc[nb][3];
        }
        s0 += __shfl_xor_sync(0xffffffffu, s0, 1); s0 += __shfl_xor_sync(0xffffffffu, s0, 2);
        q0 += __shfl_xor_sync(0xffffffffu, q0, 1); q0 += __shfl_xor_sync(0xffffffffu, q0, 2);
        s1 += __shfl_xor_sync(0xffffffffu, s1, 1); s1 += __shfl_xor_sync(0xffffffffu, s1, 2);
        q1 += __shfl_xor_sync(0xffffffffu, q1, 1); q1 += __shfl_xor_sync(0xffffffffu, q1, 2);
        float mu0 = s0 * (1.f / DD), rs0 = rsqrtf(q0 * (1.f / DD) - mu0 * mu0 + 1e-5f);
        float mu1 = s1 * (1.f / DD), rs1 = rsqrtf(q1 * (1.f / DD) - mu1 * mu1 + 1e-5f);

        // LN; pair-mean via shfl_xor(4) (partner row = row^1 -> lane^4); even rows store
        float* u0 = outp + (size_t)((base + r0) >> 1) * DD;
        float* u1 = outp + (size_t)((base + r0 + 8) >> 1) * DD;
#pragma unroll
        for (int nb = 0; nb < 16; nb++) {
            int c = nb * 8 + c0;
            float g0v = sB[128 + c], g1v = sB[128 + c + 1];
            float e0v = sB[256 + c], e1v = sB[256 + c + 1];
            float y00 = (acc[nb][0] - mu0) * rs0 * g0v + e0v;
            float y01 = (acc[nb][1] - mu0) * rs0 * g1v + e1v;
            float y10 = (acc[nb][2] - mu1) * rs1 * g0v + e0v;
            float y11 = (acc[nb][3] - mu1) * rs1 * g1v + e1v;
            float z00 = 0.5f * (y00 + __shfl_xor_sync(0xffffffffu, y00, 4));
            float z01 = 0.5f * (y01 + __shfl_xor_sync(0xffffffffu, y01, 4));
            float z10 = 0.5f * (y10 + __shfl_xor_sync(0xffffffffu, y10, 4));
            float z11 = 0.5f * (y11 + __shfl_xor_sync(0xffffffffu, y11, 4));
            if (store) {
                *reinterpret_cast<float2*>(u0 + c) = make_float2(z00, z01);
                *reinterpret_cast<float2*>(u1 + c) = make_float2(z10, z11);
            }
        }
        __syncwarp();
    }
}

// ---------------- launch ----------------
extern "C" void kernel_launch(void* const* d_in, const int* in_sizes, int n_in,
                              void* d_out, int out_size) {
    (void)in_sizes; (void)n_in; (void)out_size;
    const float* feat_A = (const float*)d_in[0];
    const float* feat_B = (const float*)d_in[1];
    const int*   src_ab = (const int*)d_in[2];
    const int*   dst_ab = (const int*)d_in[3];
    const float* val_ab = (const float*)d_in[4];
    const int*   src_ba = (const int*)d_in[5];
    const int*   dst_ba = (const int*)d_in[6];
    const float* val_ba = (const float*)d_in[7];
    const float* W1  = (const float*)d_in[8];
    const float* b1  = (const float*)d_in[9];
    const float* g1  = (const float*)d_in[10];
    const float* be1 = (const float*)d_in[11];
    const float* W2  = (const float*)d_in[12];
    const float* b2  = (const float*)d_in[13];
    const float* g2  = (const float*)d_in[14];
    const float* be2 = (const float*)d_in[15];
    const float* Win  = (const float*)d_in[16];
    const float* bin_ = (const float*)d_in[17];
    const float* Wout = (const float*)d_in[18];
    const float* bout = (const float*)d_in[19];
    const float* lng  = (const float*)d_in[20];
    const float* lnb  = (const float*)d_in[21];
    float* outp = (float*)d_out;

    cudaFuncSetAttribute(k_proj_mma, cudaFuncAttributeMaxDynamicSharedMemorySize, SMEM_PROJ_MMA);
    cudaFuncSetAttribute(k_qkv_attn, cudaFuncAttributeMaxDynamicSharedMemorySize, SMEM_QKV);
    cudaFuncSetAttribute(k_out_mma,  cudaFuncAttributeMaxDynamicSharedMemorySize, SMEM_OUT_MMA);

    // CSR build
    k_zero_cnt<<<118, 256>>>();
    k_hist<<<1875, 256>>>(dst_ab, dst_ba);
    k_scan<<<2, 1024>>>();
    k_zero_cnt<<<118, 256>>>();
    k_scatter<<<1875, 256>>>(dst_ab, src_ab, val_ab, dst_ba, src_ba, val_ba);

    // spmm + fused l2norm
    k_spmm_ab<<<7500, 256>>>(feat_A);
    k_spmm_ba<<<7500, 256>>>(feat_B);

    // mma.sync projections -> g_x
    k_proj_mma<<<GRID_GEMM, 256, SMEM_PROJ_MMA>>>(W1, b1, g1, be1, W2, b2, g2, be2);

    // fused qkv + per-head attention -> g_o (FFMA2)
    k_qkv_attn<<<GRID_GEMM, 256, SMEM_QKV>>>(Win, bin_);

    // mma.sync out-proj + residual LN + mean -> d_out
    k_out_mma<<<GRID_GEMM, 256, SMEM_OUT_MMA>>>(Wout, bout, lng, lnb, outp);
}

// round 14
// speedup vs baseline: 2.3396x; 1.2475x over previous
#include <cuda_runtime.h>
#include <cuda_bf16.h>

// ---------------- problem constants ----------------
#define N_A   30000
#define N_B   30000
#define VV    2
#define DD    128
#define EE    480000
#define PP    2

#define ROWS_H 60000    // N_A*V   (also N_B*V)
#define ROWS_X 120000   // N_A*V*P

// mma kernels: blocked bf16 tiles. W tile = 32768 B (hi or lo). A stage = 8192 B.
#define SMEM_PROJ_MMA (4*32768 + 8*8192 + 6*512)  // 199680
#define PROJ_AOFF     (4*32768)
#define PROJ_BOFF2    (4*32768 + 8*8192)
#define SMEM_OUT_MMA  (2*32768 + 8*8192 + 3*512)  // 132608
#define OUT_AOFF      (2*32768)
#define OUT_BOFF2     (2*32768 + 8*8192)
// qkv: 3 weights hi/lo (192KB) + 4 pair-shared A stages (32KB) + 3 biases
#define SMEM_QKV_MMA  (6*32768 + 4*8192 + 3*512)  // 230912 (<= 232448)
#define QKV_AOFF      (6*32768)
#define QKV_BOFF      (6*32768 + 4*8192)

#define GRID_GEMM 148

typedef unsigned long long u64;

// ---------------- scratch (device globals; no allocation allowed) ----------------
__device__ int g_cnt_ab[N_B];
__device__ int g_cnt_ba[N_A];
__device__ int g_ptr_ab[N_B + 1];
__device__ int g_ptr_ba[N_A + 1];
__device__ int   g_srcs_ab[EE];
__device__ float g_vals_ab[EE];
__device__ int   g_srcs_ba[EE];
__device__ float g_vals_ba[EE];

__device__ float g_hB  [(size_t)N_B * VV * DD];
__device__ float g_hABA[(size_t)N_A * VV * DD];
__device__ float g_hBA [(size_t)N_A * VV * DD];
__device__ float g_x[(size_t)ROWS_X * DD];
__device__ float g_o[(size_t)ROWS_X * DD];

// ---------------- generic helpers ----------------
static __device__ __forceinline__ float warp_sum(float v) {
#pragma unroll
    for (int o = 16; o > 0; o >>= 1) v += __shfl_xor_sync(0xffffffffu, v, o);
    return v;
}
static __device__ __forceinline__ unsigned smem_u32(const void* p) {
    unsigned a;
    asm("{ .reg .u64 t; cvta.to.shared.u64 t, %1; cvt.u32.u64 %0, t; }" : "=r"(a) : "l"(p));
    return a;
}

// ---------------- mma.sync helpers (sm_80-baseline ISA) ----------------
static __device__ __forceinline__ void ldsm4(unsigned* r, unsigned addr) {
    asm volatile("ldmatrix.sync.aligned.m8n8.x4.shared.b16 {%0,%1,%2,%3}, [%4];"
                 : "=r"(r[0]), "=r"(r[1]), "=r"(r[2]), "=r"(r[3]) : "r"(addr));
}
static __device__ __forceinline__ void ldsm2(unsigned& r0, unsigned& r1, unsigned addr) {
    asm volatile("ldmatrix.sync.aligned.m8n8.x2.shared.b16 {%0,%1}, [%2];"
                 : "=r"(r0), "=r"(r1) : "r"(addr));
}
static __device__ __forceinline__ void mma16816(float* d, const unsigned* a,
                                                unsigned b0, unsigned b1) {
    asm volatile("mma.sync.aligned.m16n8k16.row.col.f32.bf16.bf16.f32 "
                 "{%0,%1,%2,%3}, {%4,%5,%6,%7}, {%8,%9}, {%0,%1,%2,%3};"
                 : "+f"(d[0]), "+f"(d[1]), "+f"(d[2]), "+f"(d[3])
                 : "r"(a[0]), "r"(a[1]), "r"(a[2]), "r"(a[3]), "r"(b0), "r"(b1));
}

static __device__ __forceinline__ unsigned short bf_bits(__nv_bfloat16 h) {
    return *reinterpret_cast<unsigned short*>(&h);
}
static __device__ __forceinline__ void split4(float4 f, u64& hi, u64& lo) {
    __nv_bfloat16 h0 = __float2bfloat16(f.x), h1 = __float2bfloat16(f.y);
    __nv_bfloat16 h2 = __float2bfloat16(f.z), h3 = __float2bfloat16(f.w);
    __nv_bfloat16 l0 = __float2bfloat16(f.x - __bfloat162float(h0));
    __nv_bfloat16 l1 = __float2bfloat16(f.y - __bfloat162float(h1));
    __nv_bfloat16 l2 = __float2bfloat16(f.z - __bfloat162float(h2));
    __nv_bfloat16 l3 = __float2bfloat16(f.w - __bfloat162float(h3));
    hi = (u64)bf_bits(h0) | ((u64)bf_bits(h1) << 16)
       | ((u64)bf_bits(h2) << 32) | ((u64)bf_bits(h3) << 48);
    lo = (u64)bf_bits(l0) | ((u64)bf_bits(l1) << 16)
       | ((u64)bf_bits(l2) << 32) | ((u64)bf_bits(l3) << 48);
}

// Stage W (128x128 f32) into blocked bf16 hi/lo B-tiles (stride = blockDim).
static __device__ __forceinline__ void stage_W(char* smc, int off_hi, int off_lo,
                                               const float* W, int tid, int nthreads) {
    for (int idx = tid; idx < 4096; idx += nthreads) {
        int j = idx >> 5;
        int kq = (idx & 31) << 2;
        float4 f = *reinterpret_cast<const float4*>(W + j * DD + kq);
        u64 hi, lo; split4(f, hi, lo);
        unsigned off = (unsigned)((((j >> 3) * 8 + (kq >> 4)) * 256) +
                                  (((kq >> 3) & 1) * 128) + ((j & 7) * 16) + ((kq & 7) * 2));
        *reinterpret_cast<u64*>(smc + off_hi + off) = hi;
        *reinterpret_cast<u64*>(smc + off_lo + off) = lo;
    }
}

// Stage 16x128 f32 rows into blocked bf16 hi/lo A-tiles (one warp, 32 lanes).
static __device__ __forceinline__ void stage_A16(char* smc, int off_hi, int off_lo,
                                                 const float* src, int lane) {
#pragma unroll
    for (int i = 0; i < 16; i++) {
        int idx = lane + i * 32;
        int r = idx >> 5;
        int kq = (idx & 31) << 2;
        float4 f = *reinterpret_cast<const float4*>(src + (size_t)r * DD + kq);
        u64 hi, lo; split4(f, hi, lo);
        unsigned off = (unsigned)(((kq >> 4) * 512) +
                                  ((((r >> 3) | (((kq >> 3) & 1) << 1))) * 128) +
                                  ((r & 7) * 16) + ((kq & 7) * 2));
        *reinterpret_cast<u64*>(smc + off_hi + off) = hi;
        *reinterpret_cast<u64*>(smc + off_lo + off) = lo;
    }
}

// 3-pass bf16-split GEMM core: acc[16][4] += X(16x128) @ W^T(128x128)
static __device__ __forceinline__ void mma_core(float acc[16][4],
                                                unsigned aBaseH, unsigned aBaseL,
                                                unsigned wH, unsigned wL, int lane) {
    unsigned ah[8][4], al[8][4];
#pragma unroll
    for (int kb = 0; kb < 8; kb++) {
        ldsm4(ah[kb], aBaseH + kb * 512 + lane * 16);
        ldsm4(al[kb], aBaseL + kb * 512 + lane * 16);
    }
#pragma unroll
    for (int kb = 0; kb < 8; kb++) {
#pragma unroll
        for (int nb = 0; nb < 16; nb++) {
            unsigned boff = (unsigned)((nb * 8 + kb) * 256 + (lane & 15) * 16);
            unsigned bh0, bh1, bl0, bl1;
            ldsm2(bh0, bh1, wH + boff);
            ldsm2(bl0, bl1, wL + boff);
            mma16816(acc[nb], ah[kb], bh0, bh1);
            mma16816(acc[nb], ah[kb], bl0, bl1);
            mma16816(acc[nb], al[kb], bh0, bh1);
        }
    }
}

// ---------------- CSR build ----------------
__global__ void k_zero_cnt() {
    int i = blockIdx.x * blockDim.x + threadIdx.x;
    if (i < N_B) g_cnt_ab[i] = 0;
    if (i < N_A) g_cnt_ba[i] = 0;
}

__global__ void k_hist(const int* __restrict__ dst_ab, const int* __restrict__ dst_ba) {
    int e = blockIdx.x * blockDim.x + threadIdx.x;
    if (e < EE) {
        atomicAdd(&g_cnt_ab[dst_ab[e]], 1);
        atomicAdd(&g_cnt_ba[dst_ba[e]], 1);
    }
}

__global__ void k_scan() {
    __shared__ int ssum[1024];
    const int n = N_A;
    int* cnt = (blockIdx.x == 0) ? g_cnt_ab : g_cnt_ba;
    int* ptr = (blockIdx.x == 0) ? g_ptr_ab : g_ptr_ba;
    int t = threadIdx.x;
    const int chunk = (n + 1023) / 1024;
    int b0 = t * chunk;
    int b1 = min(b0 + chunk, n);
    int s = 0;
    for (int i = b0; i < b1; i++) s += cnt[i];
    ssum[t] = s;
    __syncthreads();
#pragma unroll
    for (int off = 1; off < 1024; off <<= 1) {
        int v = (t >= off) ? ssum[t - off] : 0;
        __syncthreads();
        ssum[t] += v;
        __syncthreads();
    }
    int run = (t == 0) ? 0 : ssum[t - 1];
    for (int i = b0; i < b1; i++) { ptr[i] = run; run += cnt[i]; }
    if (t == 1023) ptr[n] = ssum[1023];
}

__global__ void k_scatter(const int* __restrict__ dst_ab, const int* __restrict__ src_ab,
                          const float* __restrict__ val_ab,
                          const int* __restrict__ dst_ba, const int* __restrict__ src_ba,
                          const float* __restrict__ val_ba) {
    int e = blockIdx.x * blockDim.x + threadIdx.x;
    if (e < EE) {
        int d = dst_ab[e];
        int p = g_ptr_ab[d] + atomicAdd(&g_cnt_ab[d], 1);
        g_srcs_ab[p] = src_ab[e];
        g_vals_ab[p] = val_ab[e];
        d = dst_ba[e];
        p = g_ptr_ba[d] + atomicAdd(&g_cnt_ba[d], 1);
        g_srcs_ba[p] = src_ba[e];
        g_vals_ba[p] = val_ba[e];
    }
}

// ---------------- spmm + fused l2norm ----------------
__global__ void k_spmm_ab(const float* __restrict__ feat_A) {
    int w = (blockIdx.x * blockDim.x + threadIdx.x) >> 5;
    int lane = threadIdx.x & 31;
    if (w >= N_B * VV) return;
    int n = w >> 1, v = w & 1;
    int beg = g_ptr_ab[n], end = g_ptr_ab[n + 1];
    float4 acc = make_float4(0.f, 0.f, 0.f, 0.f);
    for (int c = beg; c < end; c += 32) {
        int m = min(32, end - c);
        int s = 0; float vv = 0.f;
        if (lane < m) { s = g_srcs_ab[c + lane]; vv = g_vals_ab[c + lane]; }
        int j = 0;
        for (; j + 4 <= m; j += 4) {
            int s0 = __shfl_sync(0xffffffffu, s, j);
            int s1 = __shfl_sync(0xffffffffu, s, j + 1);
            int s2 = __shfl_sync(0xffffffffu, s, j + 2);
            int s3 = __shfl_sync(0xffffffffu, s, j + 3);
            float u0 = __shfl_sync(0xffffffffu, vv, j);
            float u1 = __shfl_sync(0xffffffffu, vv, j + 1);
            float u2 = __shfl_sync(0xffffffffu, vv, j + 2);
            float u3 = __shfl_sync(0xffffffffu, vv, j + 3);
            const float4 f0 = *reinterpret_cast<const float4*>(feat_A + (((size_t)s0 * VV + v) << 7) + (lane << 2));
            const float4 f1 = *reinterpret_cast<const float4*>(feat_A + (((size_t)s1 * VV + v) << 7) + (lane << 2));
            const float4 f2 = *reinterpret_cast<const float4*>(feat_A + (((size_t)s2 * VV + v) << 7) + (lane << 2));
            const float4 f3 = *reinterpret_cast<const float4*>(feat_A + (((size_t)s3 * VV + v) << 7) + (lane << 2));
            acc.x = fmaf(f0.x, u0, acc.x); acc.y = fmaf(f0.y, u0, acc.y);
            acc.z = fmaf(f0.z, u0, acc.z); acc.w = fmaf(f0.w, u0, acc.w);
            acc.x = fmaf(f1.x, u1, acc.x); acc.y = fmaf(f1.y, u1, acc.y);
            acc.z = fmaf(f1.z, u1, acc.z); acc.w = fmaf(f1.w, u1, acc.w);
            acc.x = fmaf(f2.x, u2, acc.x); acc.y = fmaf(f2.y, u2, acc.y);
            acc.z = fmaf(f2.z, u2, acc.z); acc.w = fmaf(f2.w, u2, acc.w);
            acc.x = fmaf(f3.x, u3, acc.x); acc.y = fmaf(f3.y, u3, acc.y);
            acc.z = fmaf(f3.z, u3, acc.z); acc.w = fmaf(f3.w, u3, acc.w);
        }
        for (; j < m; j++) {
            int sj = __shfl_sync(0xffffffffu, s, j);
            float vj = __shfl_sync(0xffffffffu, vv, j);
            const float4 f = *reinterpret_cast<const float4*>(feat_A + (((size_t)sj * VV + v) << 7) + (lane << 2));
            acc.x = fmaf(f.x, vj, acc.x); acc.y = fmaf(f.y, vj, acc.y);
            acc.z = fmaf(f.z, vj, acc.z); acc.w = fmaf(f.w, vj, acc.w);
        }
    }
    float sq = warp_sum(acc.x * acc.x + acc.y * acc.y + acc.z * acc.z + acc.w * acc.w);
    float inv = 1.f / fmaxf(sqrtf(sq), 1e-12f);
    *reinterpret_cast<float4*>(g_hB + (((size_t)n * VV + v) << 7) + (lane << 2)) =
        make_float4(acc.x * inv, acc.y * inv, acc.z * inv, acc.w * inv);
}

__global__ void k_spmm_ba(const float* __restrict__ feat_B) {
    int w = (blockIdx.x * blockDim.x + threadIdx.x) >> 5;
    int lane = threadIdx.x & 31;
    if (w >= N_A * VV) return;
    int n = w >> 1, v = w & 1;
    int beg = g_ptr_ba[n], end = g_ptr_ba[n + 1];
    float4 a1 = make_float4(0.f, 0.f, 0.f, 0.f);
    float4 a2 = make_float4(0.f, 0.f, 0.f, 0.f);
    for (int c = beg; c < end; c += 32) {
        int m = min(32, end - c);
        int s = 0; float vv = 0.f;
        if (lane < m) { s = g_srcs_ba[c + lane]; vv = g_vals_ba[c + lane]; }
        int j = 0;
        for (; j + 2 <= m; j += 2) {
            int s0 = __shfl_sync(0xffffffffu, s, j);
            int s1 = __shfl_sync(0xffffffffu, s, j + 1);
            float u0 = __shfl_sync(0xffffffffu, vv, j);
            float u1 = __shfl_sync(0xffffffffu, vv, j + 1);
            size_t o0 = (((size_t)s0 * VV + v) << 7) + (lane << 2);
            size_t o1 = (((size_t)s1 * VV + v) << 7) + (lane << 2);
            const float4 p0 = *reinterpret_cast<const float4*>(g_hB + o0);
            const float4 q0 = *reinterpret_cast<const float4*>(feat_B + o0);
            const float4 p1 = *reinterpret_cast<const float4*>(g_hB + o1);
            const float4 q1 = *reinterpret_cast<const float4*>(feat_B + o1);
            a1.x = fmaf(p0.x, u0, a1.x); a1.y = fmaf(p0.y, u0, a1.y);
            a1.z = fmaf(p0.z, u0, a1.z); a1.w = fmaf(p0.w, u0, a1.w);
            a2.x = fmaf(q0.x, u0, a2.x); a2.y = fmaf(q0.y, u0, a2.y);
            a2.z = fmaf(q0.z, u0, a2.z); a2.w = fmaf(q0.w, u0, a2.w);
            a1.x = fmaf(p1.x, u1, a1.x); a1.y = fmaf(p1.y, u1, a1.y);
            a1.z = fmaf(p1.z, u1, a1.z); a1.w = fmaf(p1.w, u1, a1.w);
            a2.x = fmaf(q1.x, u1, a2.x); a2.y = fmaf(q1.y, u1, a2.y);
            a2.z = fmaf(q1.z, u1, a2.z); a2.w = fmaf(q1.w, u1, a2.w);
        }
        for (; j < m; j++) {
            int sj = __shfl_sync(0xffffffffu, s, j);
            float vj = __shfl_sync(0xffffffffu, vv, j);
            size_t off = (((size_t)sj * VV + v) << 7) + (lane << 2);
            const float4 f1 = *reinterpret_cast<const float4*>(g_hB + off);
            const float4 f2 = *reinterpret_cast<const float4*>(feat_B + off);
            a1.x = fmaf(f1.x, vj, a1.x); a1.y = fmaf(f1.y, vj, a1.y);
            a1.z = fmaf(f1.z, vj, a1.z); a1.w = fmaf(f1.w, vj, a1.w);
            a2.x = fmaf(f2.x, vj, a2.x); a2.y = fmaf(f2.y, vj, a2.y);
            a2.z = fmaf(f2.z, vj, a2.z); a2.w = fmaf(f2.w, vj, a2.w);
        }
    }
    size_t outoff = (((size_t)n * VV + v) << 7) + (lane << 2);
    float sq1 = warp_sum(a1.x * a1.x + a1.y * a1.y + a1.z * a1.z + a1.w * a1.w);
    float i1 = 1.f / fmaxf(sqrtf(sq1), 1e-12f);
    *reinterpret_cast<float4*>(g_hABA + outoff) =
        make_float4(a1.x * i1, a1.y * i1, a1.z * i1, a1.w * i1);
    float sq2 = warp_sum(a2.x * a2.x + a2.y * a2.y + a2.z * a2.z + a2.w * a2.w);
    float i2 = 1.f / fmaxf(sqrtf(sq2), 1e-12f);
    *reinterpret_cast<float4*>(g_hBA + outoff) =
        make_float4(a2.x * i2, a2.y * i2, a2.z * i2, a2.w * i2);
}

// ---------------- mma.sync proj (both matrices): relu(LN(in @ W^T + b)) -> g_x ----------------
__global__ void __launch_bounds__(256) k_proj_mma(
        const float* __restrict__ W1m, const float* __restrict__ b1m,
        const float* __restrict__ g1m, const float* __restrict__ be1m,
        const float* __restrict__ W2m, const float* __restrict__ b2m,
        const float* __restrict__ g2m, const float* __restrict__ be2m) {
    extern __shared__ char smc[];
    unsigned sbase = smem_u32(smc);
    int tid = threadIdx.x, wid = tid >> 5, lane = tid & 31;

    stage_W(smc, 0,     32768, W1m, tid, 256);
    stage_W(smc, 65536, 98304, W2m, tid, 256);
    float* sB = reinterpret_cast<float*>(smc + PROJ_BOFF2);
    if (tid < 128) {
        sB[tid]       = b1m[tid];  sB[128 + tid] = g1m[tid];  sB[256 + tid] = be1m[tid];
        sB[384 + tid] = b2m[tid];  sB[512 + tid] = g2m[tid];  sB[640 + tid] = be2m[tid];
    }
    __syncthreads();

    int aoff = PROJ_AOFF + wid * 8192;
    unsigned aBaseH = sbase + aoff, aBaseL = aBaseH + 4096;
    const int NTH = ROWS_H / 16;   // 3750
    const int c0 = 2 * (lane & 3);
    const int r0 = lane >> 2;
    for (int t = blockIdx.x * 8 + wid; t < 2 * NTH; t += GRID_GEMM * 8) {
        int which = (t >= NTH) ? 1 : 0;
        int base = (which ? (t - NTH) : t) * 16;
        const float* src = (which ? g_hBA : g_hABA) + (size_t)base * DD;
        stage_A16(smc, aoff, aoff + 4096, src, lane);
        __syncwarp();

        float acc[16][4];
#pragma unroll
        for (int nb = 0; nb < 16; nb++) {
            acc[nb][0] = acc[nb][1] = acc[nb][2] = acc[nb][3] = 0.f;
        }
        unsigned wH = sbase + which * 65536, wL = wH + 32768;
        mma_core(acc, aBaseH, aBaseL, wH, wL, lane);

        const float* bb = sB + which * 384;
        const float* gg = bb + 128;
        const float* ee = bb + 256;
        float s0 = 0.f, q0 = 0.f, s1 = 0.f, q1 = 0.f;
#pragma unroll
        for (int nb = 0; nb < 16; nb++) {
            int c = nb * 8 + c0;
            float bv0 = bb[c], bv1 = bb[c + 1];
            acc[nb][0] += bv0; acc[nb][1] += bv1;
            acc[nb][2] += bv0; acc[nb][3] += bv1;
            s0 += acc[nb][0] + acc[nb][1];
            q0 += acc[nb][0] * acc[nb][0] + acc[nb][1] * acc[nb][1];
            s1 += acc[nb][2] + acc[nb][3];
            q1 += acc[nb][2] * acc[nb][2] + acc[nb][3] * acc[nb][3];
        }
        s0 += __shfl_xor_sync(0xffffffffu, s0, 1); s0 += __shfl_xor_sync(0xffffffffu, s0, 2);
        q0 += __shfl_xor_sync(0xffffffffu, q0, 1); q0 += __shfl_xor_sync(0xffffffffu, q0, 2);
        s1 += __shfl_xor_sync(0xffffffffu, s1, 1); s1 += __shfl_xor_sync(0xffffffffu, s1, 2);
        q1 += __shfl_xor_sync(0xffffffffu, q1, 1); q1 += __shfl_xor_sync(0xffffffffu, q1, 2);
        float mu0 = s0 * (1.f / DD), rs0 = rsqrtf(q0 * (1.f / DD) - mu0 * mu0 + 1e-5f);
        float mu1 = s1 * (1.f / DD), rs1 = rsqrtf(q1 * (1.f / DD) - mu1 * mu1 + 1e-5f);

        float* o0 = g_x + ((size_t)(base + r0) * PP + which) * DD;
        float* o1 = g_x + ((size_t)(base + r0 + 8) * PP + which) * DD;
#pragma unroll
        for (int nb = 0; nb < 16; nb++) {
            int c = nb * 8 + c0;
            float g0v = gg[c], g1v = gg[c + 1], e0v = ee[c], e1v = ee[c + 1];
            *reinterpret_cast<float2*>(o0 + c) = make_float2(
                fmaxf((acc[nb][0] - mu0) * rs0 * g0v + e0v, 0.f),
                fmaxf((acc[nb][1] - mu0) * rs0 * g1v + e1v, 0.f));
            *reinterpret_cast<float2*>(o1 + c) = make_float2(
                fmaxf((acc[nb][2] - mu1) * rs1 * g0v + e0v, 0.f),
                fmaxf((acc[nb][3] - mu1) * rs1 * g1v + e1v, 0.f));
        }
        __syncwarp();
    }
}

// ---------------- mma.sync fused qkv + per-head attention -> g_o ----------------
// Warp pairs share a 16-row A stage; each warp owns 64 output cols (2 heads).
__global__ void __launch_bounds__(256) k_qkv_mma(const float* __restrict__ Win,
                                                 const float* __restrict__ bin_) {
    extern __shared__ char smc[];
    unsigned sbase = smem_u32(smc);
    int tid = threadIdx.x, wid = tid >> 5, lane = tid & 31;

    stage_W(smc, 0,      32768,  Win,               tid, 256);   // Wq
    stage_W(smc, 65536,  98304,  Win + DD * DD,     tid, 256);   // Wk
    stage_W(smc, 131072, 163840, Win + 2 * DD * DD, tid, 256);   // Wv
    float* sB = reinterpret_cast<float*>(smc + QKV_BOFF);
    if (tid < 128) {
        sB[tid] = bin_[tid];
        sB[128 + tid] = bin_[DD + tid];
        sB[256 + tid] = bin_[2 * DD + tid];
    }
    __syncthreads();

    int pairId = wid >> 1, half = wid & 1;
    int aoff = QKV_AOFF + pairId * 8192;
    unsigned aBaseH = sbase + aoff, aBaseL = aBaseH + 4096;
    unsigned wq = sbase, wk = sbase + 65536, wv = sbase + 131072;
    const float qscale = 0.17677669529663687f;
    const int NT = ROWS_X / 16;           // 7500
    const int PAIRS = GRID_GEMM * 4;      // 592
    const int NITER = (NT + PAIRS - 1) / PAIRS;   // 13 (uniform; keeps __syncthreads convergent)
    const int c0 = 2 * (lane & 3);
    const int r0 = lane >> 2;
    int gp = blockIdx.x * 4 + pairId;
    for (int it = 0; it < NITER; it++) {
        int t = gp + it * PAIRS;
        bool active = (t < NT);
        int base = active ? t * 16 : 0;
        if (active) {
            // cooperative 2-warp stage of 16x128 rows
            const float* src = g_x + (size_t)base * DD;
            int l64 = half * 32 + lane;
#pragma unroll
            for (int i = 0; i < 8; i++) {
                int idx = l64 + i * 64;
                int r = idx >> 5;
                int kq = (idx & 31) << 2;
                float4 f = *reinterpret_cast<const float4*>(src + (size_t)r * DD + kq);
                u64 hi, lo; split4(f, hi, lo);
                unsigned off = (unsigned)(((kq >> 4) * 512) +
                                          ((((r >> 3) | (((kq >> 3) & 1) << 1))) * 128) +
                                          ((r & 7) * 16) + ((kq & 7) * 2));
                *reinterpret_cast<u64*>(smc + aoff + off) = hi;
                *reinterpret_cast<u64*>(smc + aoff + 4096 + off) = lo;
            }
        }
        __syncthreads();
        if (active) {
            unsigned ah[8][4], al[8][4];
#pragma unroll
            for (int kb = 0; kb < 8; kb++) {
                ldsm4(ah[kb], aBaseH + kb * 512 + lane * 16);
                ldsm4(al[kb], aBaseL + kb * 512 + lane * 16);
            }
            // phase 1: Q, K for this warp's 8 nb blocks
            float q[8][4], k[8][4];
#pragma unroll
            for (int nbl = 0; nbl < 8; nbl++) {
                q[nbl][0] = q[nbl][1] = q[nbl][2] = q[nbl][3] = 0.f;
                k[nbl][0] = k[nbl][1] = k[nbl][2] = k[nbl][3] = 0.f;
            }
#pragma unroll
            for (int kb = 0; kb < 8; kb++) {
#pragma unroll
                for (int nbl = 0; nbl < 8; nbl++) {
                    int nb = half * 8 + nbl;
                    unsigned boff = (unsigned)((nb * 8 + kb) * 256 + (lane & 15) * 16);
                    unsigned qh0, qh1, ql0, ql1, kh0, kh1, kl0, kl1;
                    ldsm2(qh0, qh1, wq + boff);
                    ldsm2(ql0, ql1, wq + 32768 + boff);
                    ldsm2(kh0, kh1, wk + boff);
                    ldsm2(kl0, kl1, wk + 32768 + boff);
                    mma16816(q[nbl], ah[kb], qh0, qh1);
                    mma16816(k[nbl], ah[kb], kh0, kh1);
                    mma16816(q[nbl], ah[kb], ql0, ql1);
                    mma16816(k[nbl], ah[kb], kl0, kl1);
                    mma16816(q[nbl], al[kb], qh0, qh1);
                    mma16816(k[nbl], al[kb], kh0, kh1);
                }
            }
            // biases
#pragma unroll
            for (int nbl = 0; nbl < 8; nbl++) {
                int c = (half * 8 + nbl) * 8 + c0;
                float bq0 = sB[c], bq1 = sB[c + 1];
                float bk0 = sB[128 + c], bk1 = sB[128 + c + 1];
                q[nbl][0] += bq0; q[nbl][1] += bq1; q[nbl][2] += bq0; q[nbl][3] += bq1;
                k[nbl][0] += bk0; k[nbl][1] += bk1; k[nbl][2] += bk0; k[nbl][3] += bk1;
            }
            // per-head scores + softmax (2 local heads); partner row via shfl_xor(4)
            float aw[8];
#pragma unroll
            for (int hl = 0; hl < 2; hl++) {
                float pss0 = 0.f, psp0 = 0.f, pss1 = 0.f, psp1 = 0.f;
#pragma unroll
                for (int i = 0; i < 4; i++) {
                    int nbl = hl * 4 + i;
                    float kp0 = __shfl_xor_sync(0xffffffffu, k[nbl][0], 4);
                    float kp1 = __shfl_xor_sync(0xffffffffu, k[nbl][1], 4);
                    float kp2 = __shfl_xor_sync(0xffffffffu, k[nbl][2], 4);
                    float kp3 = __shfl_xor_sync(0xffffffffu, k[nbl][3], 4);
                    pss0 += q[nbl][0] * k[nbl][0] + q[nbl][1] * k[nbl][1];
                    psp0 += q[nbl][0] * kp0 + q[nbl][1] * kp1;
                    pss1 += q[nbl][2] * k[nbl][2] + q[nbl][3] * k[nbl][3];
                    psp1 += q[nbl][2] * kp2 + q[nbl][3] * kp3;
                }
                pss0 += __shfl_xor_sync(0xffffffffu, pss0, 1);
                pss0 += __shfl_xor_sync(0xffffffffu, pss0, 2);
                psp0 += __shfl_xor_sync(0xffffffffu, psp0, 1);
                psp0 += __shfl_xor_sync(0xffffffffu, psp0, 2);
                pss1 += __shfl_xor_sync(0xffffffffu, pss1, 1);
                pss1 += __shfl_xor_sync(0xffffffffu, pss1, 2);
                psp1 += __shfl_xor_sync(0xffffffffu, psp1, 1);
                psp1 += __shfl_xor_sync(0xffffffffu, psp1, 2);
                pss0 *= qscale; psp0 *= qscale; pss1 *= qscale; psp1 *= qscale;
                float m0 = fmaxf(pss0, psp0), m1 = fmaxf(pss1, psp1);
                float es0 = expf(pss0 - m0), ep0 = expf(psp0 - m0);
                float es1 = expf(pss1 - m1), ep1 = expf(psp1 - m1);
                float i0 = 1.f / (es0 + ep0), i1 = 1.f / (es1 + ep1);
                aw[hl * 4 + 0] = es0 * i0;
                aw[hl * 4 + 1] = ep0 * i0;
                aw[hl * 4 + 2] = es1 * i1;
                aw[hl * 4 + 3] = ep1 * i1;
            }
            // phase 2: V (interleave pairs of nbl for dependency spacing)
            float v[8][4];
#pragma unroll
            for (int nbl = 0; nbl < 8; nbl++) {
                v[nbl][0] = v[nbl][1] = v[nbl][2] = v[nbl][3] = 0.f;
            }
#pragma unroll
            for (int kb = 0; kb < 8; kb++) {
#pragma unroll
                for (int nbl = 0; nbl < 8; nbl += 2) {
                    int nb = half * 8 + nbl;
                    unsigned boffA = (unsigned)((nb * 8 + kb) * 256 + (lane & 15) * 16);
                    unsigned boffB = boffA + 2048;   // nbl+1: +8*256
                    unsigned vhA0, vhA1, vlA0, vlA1, vhB0, vhB1, vlB0, vlB1;
                    ldsm2(vhA0, vhA1, wv + boffA);
                    ldsm2(vlA0, vlA1, wv + 32768 + boffA);
                    ldsm2(vhB0, vhB1, wv + boffB);
                    ldsm2(vlB0, vlB1, wv + 32768 + boffB);
                    mma16816(v[nbl],     ah[kb], vhA0, vhA1);
                    mma16816(v[nbl + 1], ah[kb], vhB0, vhB1);
                    mma16816(v[nbl],     ah[kb], vlA0, vlA1);
                    mma16816(v[nbl + 1], ah[kb], vlB0, vlB1);
                    mma16816(v[nbl],     al[kb], vhA0, vhA1);
                    mma16816(v[nbl + 1], al[kb], vhB0, vhB1);
                }
            }
            // combine: o = a_ss*v_self + a_sp*v_partner, write g_o
            float* o0row = g_o + (size_t)(base + r0) * DD;
            float* o1row = g_o + (size_t)(base + r0 + 8) * DD;
#pragma unroll
            for (int nbl = 0; nbl < 8; nbl++) {
                int c = (half * 8 + nbl) * 8 + c0;
                int hl = nbl >> 2;
                float bv0 = sB[256 + c], bv1 = sB[256 + c + 1];
                float v0 = v[nbl][0] + bv0, v1 = v[nbl][1] + bv1;
                float v2 = v[nbl][2] + bv0, v3 = v[nbl][3] + bv1;
                float vp0 = __shfl_xor_sync(0xffffffffu, v0, 4);
                float vp1 = __shfl_xor_sync(0xffffffffu, v1, 4);
                float vp2 = __shfl_xor_sync(0xffffffffu, v2, 4);
                float vp3 = __shfl_xor_sync(0xffffffffu, v3, 4);
                *reinterpret_cast<float2*>(o0row + c) = make_float2(
                    aw[hl * 4 + 0] * v0 + aw[hl * 4 + 1] * vp0,
                    aw[hl * 4 + 0] * v1 + aw[hl * 4 + 1] * vp1);
                *reinterpret_cast<float2*>(o1row + c) = make_float2(
                    aw[hl * 4 + 2] * v2 + aw[hl * 4 + 3] * vp2,
                    aw[hl * 4 + 2] * v3 + aw[hl * 4 + 3] * vp3);
            }
        }
        __syncthreads();
    }
}

// ---------------- mma.sync out: g_o @ Wout^T + bout; LN(+g_x); mean over P -> d_out ----------------
__global__ void __launch_bounds__(256) k_out_mma(
        const float* __restrict__ Wm, const float* __restrict__ bm,
        const float* __restrict__ gm, const float* __restrict__ bem,
        float* __restrict__ outp) {
    extern __shared__ char smc[];
    unsigned sbase = smem_u32(smc);
    int tid = threadIdx.x, wid = tid >> 5, lane = tid & 31;

    stage_W(smc, 0, 32768, Wm, tid, 256);
    float* sB = reinterpret_cast<float*>(smc + OUT_BOFF2);
    if (tid < 128) {
        sB[tid] = bm[tid];  sB[128 + tid] = gm[tid];  sB[256 + tid] = bem[tid];
    }
    __syncthreads();

    int aoff = OUT_AOFF + wid * 8192;
    unsigned aBaseH = sbase + aoff, aBaseL = aBaseH + 4096;
    unsigned wH = sbase, wL = sbase + 32768;
    const int NT = ROWS_X / 16;
    const int c0 = 2 * (lane & 3);
    const int r0 = lane >> 2;
    const bool store = (lane & 4) == 0;
    for (int t = blockIdx.x * 8 + wid; t < NT; t += GRID_GEMM * 8) {
        int base = t * 16;
        stage_A16(smc, aoff, aoff + 4096, g_o + (size_t)base * DD, lane);
        __syncwarp();

        float acc[16][4];
#pragma unroll
        for (int nb = 0; nb < 16; nb++) {
            acc[nb][0] = acc[nb][1] = acc[nb][2] = acc[nb][3] = 0.f;
        }
        mma_core(acc, aBaseH, aBaseL, wH, wL, lane);

        const float* xr0 = g_x + (size_t)(base + r0) * DD;
        const float* xr1 = g_x + (size_t)(base + r0 + 8) * DD;
        float s0 = 0.f, q0 = 0.f, s1 = 0.f, q1 = 0.f;
#pragma unroll
        for (int nb = 0; nb < 16; nb++) {
            int c = nb * 8 + c0;
            float2 x0 = *reinterpret_cast<const float2*>(xr0 + c);
            float2 x1 = *reinterpret_cast<const float2*>(xr1 + c);
            float bv0 = sB[c], bv1 = sB[c + 1];
            acc[nb][0] += bv0 + x0.x;  acc[nb][1] += bv1 + x0.y;
            acc[nb][2] += bv0 + x1.x;  acc[nb][3] += bv1 + x1.y;
            s0 += acc[nb][0] + acc[nb][1];
            q0 += acc[nb][0] * acc[nb][0] + acc[nb][1] * acc[nb][1];
            s1 += acc[nb][2] + acc[nb][3];
            q1 += acc[nb][2] * acc[nb][2] + acc[nb][3] * acc[nb][3];
        }
        s0 += __shfl_xor_sync(0xffffffffu, s0, 1); s0 += __shfl_xor_sync(0xffffffffu, s0, 2);
        q0 += __shfl_xor_sync(0xffffffffu, q0, 1); q0 += __shfl_xor_sync(0xffffffffu, q0, 2);
        s1 += __shfl_xor_sync(0xffffffffu, s1, 1); s1 += __shfl_xor_sync(0xffffffffu, s1, 2);
        q1 += __shfl_xor_sync(0xffffffffu, q1, 1); q1 += __shfl_xor_sync(0xffffffffu, q1, 2);
        float mu0 = s0 * (1.f / DD), rs0 = rsqrtf(q0 * (1.f / DD) - mu0 * mu0 + 1e-5f);
        float mu1 = s1 * (1.f / DD), rs1 = rsqrtf(q1 * (1.f / DD) - mu1 * mu1 + 1e-5f);

        float* u0 = outp + (size_t)((base + r0) >> 1) * DD;
        float* u1 = outp + (size_t)((base + r0 + 8) >> 1) * DD;
#pragma unroll
        for (int nb = 0; nb < 16; nb++) {
            int c = nb * 8 + c0;
            float g0v = sB[128 + c], g1v = sB[128 + c + 1];
            float e0v = sB[256 + c], e1v = sB[256 + c + 1];
            float y00 = (acc[nb][0] - mu0) * rs0 * g0v + e0v;
            float y01 = (acc[nb][1] - mu0) * rs0 * g1v + e1v;
            float y10 = (acc[nb][2] - mu1) * rs1 * g0v + e0v;
            float y11 = (acc[nb][3] - mu1) * rs1 * g1v + e1v;
            float z00 = 0.5f * (y00 + __shfl_xor_sync(0xffffffffu, y00, 4));
            float z01 = 0.5f * (y01 + __shfl_xor_sync(0xffffffffu, y01, 4));
            float z10 = 0.5f * (y10 + __shfl_xor_sync(0xffffffffu, y10, 4));
            float z11 = 0.5f * (y11 + __shfl_xor_sync(0xffffffffu, y11, 4));
            if (store) {
                *reinterpret_cast<float2*>(u0 + c) = make_float2(z00, z01);
                *reinterpret_cast<float2*>(u1 + c) = make_float2(z10, z11);
            }
        }
        __syncwarp();
    }
}

// ---------------- launch ----------------
extern "C" void kernel_launch(void* const* d_in, const int* in_sizes, int n_in,
                              void* d_out, int out_size) {
    (void)in_sizes; (void)n_in; (void)out_size;
    const float* feat_A = (const float*)d_in[0];
    const float* feat_B = (const float*)d_in[1];
    const int*   src_ab = (const int*)d_in[2];
    const int*   dst_ab = (const int*)d_in[3];
    const float* val_ab = (const float*)d_in[4];
    const int*   src_ba = (const int*)d_in[5];
    const int*   dst_ba = (const int*)d_in[6];
    const float* val_ba = (const float*)d_in[7];
    const float* W1  = (const float*)d_in[8];
    const float* b1  = (const float*)d_in[9];
    const float* g1  = (const float*)d_in[10];
    const float* be1 = (const float*)d_in[11];
    const float* W2  = (const float*)d_in[12];
    const float* b2  = (const float*)d_in[13];
    const float* g2  = (const float*)d_in[14];
    const float* be2 = (const float*)d_in[15];
    const float* Win  = (const float*)d_in[16];
    const float* bin_ = (const float*)d_in[17];
    const float* Wout = (const float*)d_in[18];
    const float* bout = (const float*)d_in[19];
    const float* lng  = (const float*)d_in[20];
    const float* lnb  = (const float*)d_in[21];
    float* outp = (float*)d_out;

    cudaFuncSetAttribute(k_proj_mma, cudaFuncAttributeMaxDynamicSharedMemorySize, SMEM_PROJ_MMA);
    cudaFuncSetAttribute(k_qkv_mma,  cudaFuncAttributeMaxDynamicSharedMemorySize, SMEM_QKV_MMA);
    cudaFuncSetAttribute(k_out_mma,  cudaFuncAttributeMaxDynamicSharedMemorySize, SMEM_OUT_MMA);

    // CSR build
    k_zero_cnt<<<118, 256>>>();
    k_hist<<<1875, 256>>>(dst_ab, dst_ba);
    k_scan<<<2, 1024>>>();
    k_zero_cnt<<<118, 256>>>();
    k_scatter<<<1875, 256>>>(dst_ab, src_ab, val_ab, dst_ba, src_ba, val_ba);

    // spmm + fused l2norm
    k_spmm_ab<<<7500, 256>>>(feat_A);
    k_spmm_ba<<<7500, 256>>>(feat_B);

    // mma.sync projections -> g_x
    k_proj_mma<<<GRID_GEMM, 256, SMEM_PROJ_MMA>>>(W1, b1, g1, be1, W2, b2, g2, be2);

    // mma.sync fused qkv + per-head attention -> g_o
    k_qkv_mma<<<GRID_GEMM, 256, SMEM_QKV_MMA>>>(Win, bin_);

    // mma.sync out-proj + residual LN + mean -> d_out
    k_out_mma<<<GRID_GEMM, 256, SMEM_OUT_MMA>>>(Wout, bout, lng, lnb, outp);
}